// round 1
// baseline (speedup 1.0000x reference)
#include <cuda_runtime.h>
#include <math_constants.h>
#include <cstdint>
#include <cstddef>

// Problem constants
namespace cfg {
constexpr int B = 8, T = 512, C = 1024, H = 16, E = 64, L = 2048;
constexpr int M = B * T;        // 4096 rows for both GEMMs
constexpr int NQKV = 3 * C;     // 3072
constexpr int NCT = L / 64;     // 32 cache key-tiles
}

// Scratch (device globals — no allocation allowed)
__device__ float g_q[cfg::B * cfg::H * cfg::T * cfg::E];   // (B,H,T,E)
__device__ float g_k[cfg::B * cfg::H * cfg::T * cfg::E];
__device__ float g_v[cfg::B * cfg::H * cfg::T * cfg::E];
__device__ float g_y[cfg::B * cfg::T * cfg::C];            // (B,T,C) attention out

// ---------------------------------------------------------------------------
// 64x64 tiled fp32 GEMM, K=1024, 256 threads, 4x4 per thread.
// MODE 0: out = X @ Wqkv + b, scattered into g_q/g_k/g_v as (B,H,T,E)
// MODE 1: out = g_y @ Wproj + b, written densely to `out`
// ---------------------------------------------------------------------------
template <int N, int MODE>
__global__ __launch_bounds__(256) void gemm64x64(const float* __restrict__ A,
                                                 const float* __restrict__ W,
                                                 const float* __restrict__ bias,
                                                 float* __restrict__ out) {
    __shared__ float As[16][68];   // transposed A tile: As[k][m]
    __shared__ float Bs[16][68];   // Bs[k][n]

    const int tid = threadIdx.x;
    const int tx = tid & 15;       // n sub-tile
    const int ty = tid >> 4;       // m sub-tile
    const int m0 = blockIdx.y * 64;
    const int n0 = blockIdx.x * 64;

    const float* Abase = (MODE == 1) ? g_y : A;

    // loader mapping
    const int ar = tid >> 2;            // A row 0..63
    const int ak = (tid & 3) * 4;       // A k-subcol 0..12
    const int br = tid >> 4;            // B k-row 0..15
    const int bc = (tid & 15) * 4;      // B n-col 0..60

    float acc[4][4] = {};

    const float* Aptr = Abase + (size_t)(m0 + ar) * cfg::C + ak;
    const float* Wptr = W + (size_t)br * N + n0 + bc;

    for (int k0 = 0; k0 < cfg::C; k0 += 16) {
        float4 av = *(const float4*)(Aptr + k0);
        float4 bv = *(const float4*)(Wptr + (size_t)k0 * N);
        __syncthreads();
        As[ak + 0][ar] = av.x;
        As[ak + 1][ar] = av.y;
        As[ak + 2][ar] = av.z;
        As[ak + 3][ar] = av.w;
        *(float4*)&Bs[br][bc] = bv;
        __syncthreads();
#pragma unroll
        for (int kk = 0; kk < 16; kk++) {
            float4 a = *(const float4*)&As[kk][ty * 4];
            float4 b = *(const float4*)&Bs[kk][tx * 4];
            acc[0][0] += a.x * b.x; acc[0][1] += a.x * b.y; acc[0][2] += a.x * b.z; acc[0][3] += a.x * b.w;
            acc[1][0] += a.y * b.x; acc[1][1] += a.y * b.y; acc[1][2] += a.y * b.z; acc[1][3] += a.y * b.w;
            acc[2][0] += a.z * b.x; acc[2][1] += a.z * b.y; acc[2][2] += a.z * b.z; acc[2][3] += a.z * b.w;
            acc[3][0] += a.w * b.x; acc[3][1] += a.w * b.y; acc[3][2] += a.w * b.z; acc[3][3] += a.w * b.w;
        }
    }

    const float4 b4 = *(const float4*)&bias[n0 + tx * 4];

    if (MODE == 0) {
        // scatter qkv -> (B,H,T,E). n-tile is 64-aligned so head is fixed.
        const int n = n0 + tx * 4;
        const int sel = n >> 10;          // 0=q,1=k,2=v
        const int c = n & 1023;
        const int h = c >> 6;
        const int e0 = c & 63;            // multiple of 4
        float* dst = (sel == 0) ? g_q : (sel == 1) ? g_k : g_v;
#pragma unroll
        for (int i = 0; i < 4; i++) {
            const int m = m0 + ty * 4 + i;
            const int b = m >> 9;
            const int t = m & 511;
            float4 o;
            o.x = acc[i][0] + b4.x;
            o.y = acc[i][1] + b4.y;
            o.z = acc[i][2] + b4.z;
            o.w = acc[i][3] + b4.w;
            *(float4*)&dst[(((size_t)(b * cfg::H + h) * cfg::T) + t) * cfg::E + e0] = o;
        }
    } else {
#pragma unroll
        for (int i = 0; i < 4; i++) {
            const int m = m0 + ty * 4 + i;
            float4 o;
            o.x = acc[i][0] + b4.x;
            o.y = acc[i][1] + b4.y;
            o.z = acc[i][2] + b4.z;
            o.w = acc[i][3] + b4.w;
            *(float4*)&out[(size_t)m * N + n0 + tx * 4] = o;
        }
    }
}

// ---------------------------------------------------------------------------
// Flash attention: one block per (q-tile of 64, head, batch).
// 256 threads: thread (qg,jg) owns q rows qg*4..+3.
//   scores: 4q x 4j block (j = jg + 16*ji), full E=64 dot products
//   PV:     4q x 4e block (e = jg*4..+3), probabilities via smem row
// Keys iterate 32 cache tiles + (qt+1) new tiles; only the kt==qt tile masks.
// ---------------------------------------------------------------------------
__global__ __launch_bounds__(256) void attn_kernel(const float* __restrict__ kc,
                                                   const float* __restrict__ vc) {
    constexpr int STR = 68;
    extern __shared__ float sm[];
    float* q_s = sm;                 // 64 x STR
    float* k_s = sm + 64 * STR;
    float* v_s = sm + 2 * 64 * STR;
    float* p_s = sm + 3 * 64 * STR;

    const int qt = blockIdx.x;
    const int h = blockIdx.y;
    const int b = blockIdx.z;
    const int tid = threadIdx.x;
    const int qg = tid >> 4;   // 0..15
    const int jg = tid & 15;   // 0..15
    const int i0 = qt * 64;

    const size_t bh = (size_t)b * cfg::H + h;
    const float* qbase = g_q + (bh * cfg::T + i0) * cfg::E;
    const float* kcb = kc + bh * cfg::L * cfg::E;
    const float* vcb = vc + bh * cfg::L * cfg::E;
    const float* knb = g_k + bh * cfg::T * cfg::E;
    const float* vnb = g_v + bh * cfg::T * cfg::E;

    // load Q tile (64x64)
#pragma unroll
    for (int r = 0; r < 4; r++) {
        const int fi = r * 256 + tid;
        const int row = fi >> 4;
        const int c4 = (fi & 15) * 4;
        *(float4*)&q_s[row * STR + c4] = *(const float4*)&qbase[row * 64 + c4];
    }

    float m_i[4], l_i[4], accv[4][4];
#pragma unroll
    for (int qi = 0; qi < 4; qi++) {
        m_i[qi] = -CUDART_INF_F;
        l_i[qi] = 0.f;
#pragma unroll
        for (int ei = 0; ei < 4; ei++) accv[qi][ei] = 0.f;
    }

    const int ntiles = cfg::NCT + qt + 1;
    const float scale = 0.125f;  // 1/sqrt(64)

    for (int tIdx = 0; tIdx < ntiles; tIdx++) {
        const float* ksrc;
        const float* vsrc;
        bool diag = false;
        if (tIdx < cfg::NCT) {
            ksrc = kcb + (size_t)tIdx * 64 * cfg::E;
            vsrc = vcb + (size_t)tIdx * 64 * cfg::E;
        } else {
            const int kt = tIdx - cfg::NCT;
            ksrc = knb + (size_t)kt * 64 * cfg::E;
            vsrc = vnb + (size_t)kt * 64 * cfg::E;
            diag = (kt == qt);
        }
        __syncthreads();
#pragma unroll
        for (int r = 0; r < 4; r++) {
            const int fi = r * 256 + tid;
            const int row = fi >> 4;
            const int c4 = (fi & 15) * 4;
            *(float4*)&k_s[row * STR + c4] = *(const float4*)&ksrc[row * 64 + c4];
            *(float4*)&v_s[row * STR + c4] = *(const float4*)&vsrc[row * 64 + c4];
        }
        __syncthreads();

        // ---- scores: s[qi][ji] = q(row qg*4+qi) . k(row jg+16*ji)
        float s[4][4] = {};
#pragma unroll 2
        for (int e0 = 0; e0 < 64; e0 += 4) {
            float4 qv[4];
#pragma unroll
            for (int qi = 0; qi < 4; qi++)
                qv[qi] = *(const float4*)&q_s[(qg * 4 + qi) * STR + e0];
#pragma unroll
            for (int ji = 0; ji < 4; ji++) {
                const float4 kv = *(const float4*)&k_s[(jg + 16 * ji) * STR + e0];
#pragma unroll
                for (int qi = 0; qi < 4; qi++) {
                    s[qi][ji] += qv[qi].x * kv.x + qv[qi].y * kv.y
                               + qv[qi].z * kv.z + qv[qi].w * kv.w;
                }
            }
        }

        // ---- online softmax (row group = 16 threads sharing qg)
#pragma unroll
        for (int qi = 0; qi < 4; qi++) {
            float sr[4];
#pragma unroll
            for (int ji = 0; ji < 4; ji++) {
                float v = s[qi][ji] * scale;
                if (diag && (jg + 16 * ji > qg * 4 + qi)) v = -CUDART_INF_F;
                sr[ji] = v;
            }
            float tm = fmaxf(fmaxf(sr[0], sr[1]), fmaxf(sr[2], sr[3]));
#pragma unroll
            for (int o = 1; o < 16; o <<= 1)
                tm = fmaxf(tm, __shfl_xor_sync(0xffffffffu, tm, o));
            const float mn = fmaxf(m_i[qi], tm);
            const float corr = __expf(m_i[qi] - mn);
            m_i[qi] = mn;
            float ps = 0.f;
#pragma unroll
            for (int ji = 0; ji < 4; ji++) {
                const float p = __expf(sr[ji] - mn);
                ps += p;
                p_s[(qg * 4 + qi) * STR + jg + 16 * ji] = p;
            }
#pragma unroll
            for (int o = 1; o < 16; o <<= 1)
                ps += __shfl_xor_sync(0xffffffffu, ps, o);
            l_i[qi] = l_i[qi] * corr + ps;
#pragma unroll
            for (int ei = 0; ei < 4; ei++) accv[qi][ei] *= corr;
        }
        __syncwarp();

        // ---- PV: acc[qi][e] += sum_j p[q][j] * v[j][e], e = jg*4..+3
#pragma unroll 4
        for (int j = 0; j < 64; j++) {
            const float4 vv = *(const float4*)&v_s[j * STR + jg * 4];
#pragma unroll
            for (int qi = 0; qi < 4; qi++) {
                const float pj = p_s[(qg * 4 + qi) * STR + j];
                accv[qi][0] += pj * vv.x;
                accv[qi][1] += pj * vv.y;
                accv[qi][2] += pj * vv.z;
                accv[qi][3] += pj * vv.w;
            }
        }
        __syncwarp();
    }

    // ---- epilogue: y[b, t, h*64 + e] = acc / l
#pragma unroll
    for (int qi = 0; qi < 4; qi++) {
        const float inv = 1.f / l_i[qi];
        float4 o;
        o.x = accv[qi][0] * inv;
        o.y = accv[qi][1] * inv;
        o.z = accv[qi][2] * inv;
        o.w = accv[qi][3] * inv;
        const int trow = i0 + qg * 4 + qi;
        *(float4*)&g_y[((size_t)b * cfg::T + trow) * cfg::C + h * cfg::E + jg * 4] = o;
    }
}

// ---------------------------------------------------------------------------
extern "C" void kernel_launch(void* const* d_in, const int* in_sizes, int n_in,
                              void* d_out, int out_size) {
    const float* x     = (const float*)d_in[0];
    const float* kcch  = (const float*)d_in[1];
    const float* vcch  = (const float*)d_in[2];
    const float* Wqkv  = (const float*)d_in[3];
    const float* bqkv  = (const float*)d_in[4];
    const float* Wproj = (const float*)d_in[5];
    const float* bproj = (const float*)d_in[6];
    float* out = (float*)d_out;

    const int attn_smem = 4 * 64 * 68 * (int)sizeof(float);  // 69632 B
    cudaFuncSetAttribute(attn_kernel, cudaFuncAttributeMaxDynamicSharedMemorySize,
                         attn_smem);

    // 1) QKV projection + head split
    gemm64x64<cfg::NQKV, 0><<<dim3(cfg::NQKV / 64, cfg::M / 64), 256>>>(
        x, Wqkv, bqkv, nullptr);

    // 2) Flash attention over cache + new keys
    attn_kernel<<<dim3(cfg::T / 64, cfg::H, cfg::B), 256, attn_smem>>>(kcch, vcch);

    // 3) Output projection
    gemm64x64<cfg::C, 1><<<dim3(cfg::C / 64, cfg::M / 64), 256>>>(
        nullptr, Wproj, bproj, out);
}

// round 6
// speedup vs baseline: 1.3361x; 1.3361x over previous
#include <cuda_runtime.h>
#include <math_constants.h>
#include <cstdint>
#include <cstddef>

// Problem constants
namespace cfg {
constexpr int B = 8, T = 512, C = 1024, H = 16, E = 64, L = 2048;
constexpr int M = B * T;        // 4096 rows for both GEMMs
constexpr int NQKV = 3 * C;     // 3072
constexpr int NCT = L / 64;     // 32 cache key-tiles
}

// Scratch (device globals — no allocation allowed)
__device__ float g_q[cfg::B * cfg::H * cfg::T * cfg::E];   // (B,H,T,E)
__device__ float g_k[cfg::B * cfg::H * cfg::T * cfg::E];
__device__ float g_v[cfg::B * cfg::H * cfg::T * cfg::E];
__device__ float g_y[cfg::B * cfg::T * cfg::C];            // (B,T,C) attention out

// ---------------------------------------------------------------------------
// mma.sync helpers (portable PTX, works at compute_103 base target)
// ---------------------------------------------------------------------------
__device__ __forceinline__ uint32_t f2tf32(float x) {
    uint32_t r;
    asm("cvt.rna.tf32.f32 %0, %1;" : "=r"(r) : "f"(x));
    return r;
}

// D(16x8,f32) += A(16x8,tf32) * B(8x8,tf32)
__device__ __forceinline__ void mma_tf32(float* d, const uint32_t* a,
                                         const uint32_t* b) {
    asm volatile(
        "mma.sync.aligned.m16n8k8.row.col.f32.tf32.tf32.f32 "
        "{%0,%1,%2,%3}, {%4,%5,%6,%7}, {%8,%9}, {%0,%1,%2,%3};"
        : "+f"(d[0]), "+f"(d[1]), "+f"(d[2]), "+f"(d[3])
        : "r"(a[0]), "r"(a[1]), "r"(a[2]), "r"(a[3]), "r"(b[0]), "r"(b[1]));
}

// ---------------------------------------------------------------------------
// tf32 mma.sync GEMM: 128x128 tile per CTA, K=1024 in chunks of 32,
// double-buffered fragment-order SMEM. 256 threads = 8 warps (2m x 4n),
// warp tile 64x32 = 4x4 frags of m16n8k8.
// MODE 0: out = X @ Wqkv + b   -> scattered into g_q/g_k/g_v as (B,H,T,E)
// MODE 1: out = g_y @ Wproj + b -> dense `out`
// A [M,1024] row-major. W [1024][N] row-major (k-major rows == mma B layout).
//
// SMEM (u32 units):
//   Af[buf][mf(8)][ks(4)][lane(32)][slot(4)]  base 0      (8192 u32)
//   Bf[buf][nf(16)][ks(4)][lane(32)][slot(2)] base 8192   (8192 u32)
//   bias[128]                                  base 16384
// Physical lane is XOR-swizzled: A: lane^(ks<<2), B: lane^((nf&3)<<2).
// ---------------------------------------------------------------------------
constexpr int GM_SMEM_U32 = 8192 + 8192 + 128;
constexpr int GM_SMEM_BYTES = GM_SMEM_U32 * 4;   // 66048

template <int N, int MODE>
__global__ __launch_bounds__(256) void gemm_mma(const float* __restrict__ Ag,
                                                const float* __restrict__ W,
                                                const float* __restrict__ bias,
                                                float* __restrict__ out) {
    extern __shared__ uint32_t sh[];
    float* biasS = (float*)(sh + 16384);

    const int t = threadIdx.x;
    const int lane = t & 31;
    const int wid = t >> 5;
    const int wm = wid >> 2;     // 0..1
    const int wn = wid & 3;      // 0..3
    const int m0 = blockIdx.y * 128;
    const int n0 = blockIdx.x * 128;

    const float* Abase = (MODE == 1) ? g_y : Ag;
    if (t < 128) biasS[t] = bias[n0 + t];

    float acc[4][4][4];
#pragma unroll
    for (int im = 0; im < 4; im++)
#pragma unroll
        for (int in = 0; in < 4; in++)
#pragma unroll
            for (int k = 0; k < 4; k++) acc[im][in][k] = 0.f;

    // ---- loader index precompute ----
    // A: lane covers row = (t>>3) + 32*i, float4 k-col kq = t&7
    const int a_row_b = t >> 3;          // + 32*i
    const int a_kq = t & 7;
    // B: lane covers k-row kr = t>>3, n float4 col nq = (t&7) + 8*i
    const int b_kr = t >> 3;
    const int b_nq_b = t & 7;            // + 8*i

    auto loadA = [&](int ck, float4* av) {
#pragma unroll
        for (int i = 0; i < 4; i++) {
            const int row = a_row_b + 32 * i;
            av[i] = *(const float4*)(Abase + (size_t)(m0 + row) * cfg::C +
                                     ck * 32 + a_kq * 4);
        }
    };
    auto loadB = [&](int ck, float4* bv) {
#pragma unroll
        for (int i = 0; i < 4; i++) {
            const int nq = b_nq_b + 8 * i;
            bv[i] = *(const float4*)(W + (size_t)(ck * 32 + b_kr) * N + n0 +
                                     nq * 4);
        }
    };
    auto storeA = [&](int buf, const float4* av) {
#pragma unroll
        for (int i = 0; i < 4; i++) {
            const int row = a_row_b + 32 * i;
            const int mf = row >> 4;
            const int r = row & 15;
            const int ks = a_kq >> 1;
            const int slot = ((a_kq & 1) << 1) | (r >> 3);
            const int lb = (r & 7) << 2;
            const float* vv = (const float*)&av[i];
#pragma unroll
            for (int j = 0; j < 4; j++) {
                const int pl = (lb + j) ^ (ks << 2);
                sh[((((buf * 8 + mf) * 4 + ks) * 32 + pl) << 2) + slot] =
                    f2tf32(vv[j]);
            }
        }
    };
    auto storeB = [&](int buf, const float4* bv) {
#pragma unroll
        for (int i = 0; i < 4; i++) {
            const int nq = b_nq_b + 8 * i;
            const int nf = nq >> 1;
            const int ks = b_kr >> 3;
            const int slot = (b_kr >> 2) & 1;
            const int lb = ((nq & 1) << 4) | (b_kr & 3);
            const float* vv = (const float*)&bv[i];
#pragma unroll
            for (int j = 0; j < 4; j++) {
                const int pl = (lb + (j << 2)) ^ ((nf & 3) << 2);
                sh[8192 + ((((buf * 16 + nf) * 4 + ks) * 32 + pl) << 1) + slot] =
                    f2tf32(vv[j]);
            }
        }
    };

    auto compute = [&](int buf) {
#pragma unroll
        for (int ks = 0; ks < 4; ks++) {
            uint32_t a[4][4];
            uint32_t b[4][2];
#pragma unroll
            for (int im = 0; im < 4; im++) {
                const int mf = wm * 4 + im;
                const int pl = lane ^ (ks << 2);
                uint4 v = *(const uint4*)&sh[(((buf * 8 + mf) * 4 + ks) * 32 + pl) << 2];
                a[im][0] = v.x; a[im][1] = v.y; a[im][2] = v.z; a[im][3] = v.w;
            }
#pragma unroll
            for (int in = 0; in < 4; in++) {
                const int nf = wn * 4 + in;
                const int pl = lane ^ ((nf & 3) << 2);
                uint2 v = *(const uint2*)&sh[8192 + ((((buf * 16 + nf) * 4 + ks) * 32 + pl) << 1)];
                b[in][0] = v.x; b[in][1] = v.y;
            }
#pragma unroll
            for (int im = 0; im < 4; im++)
#pragma unroll
                for (int in = 0; in < 4; in++)
                    mma_tf32(acc[im][in], a[im], b[in]);
        }
    };

    // ---- mainloop: prefetch-to-regs, double-buffered smem ----
    {
        float4 av[4], bv[4];
        loadA(0, av); loadB(0, bv);
        storeA(0, av); storeB(0, bv);
    }
    __syncthreads();
    for (int ck = 0; ck < 32; ck++) {
        float4 av[4], bv[4];
        if (ck < 31) { loadA(ck + 1, av); loadB(ck + 1, bv); }
        compute(ck & 1);
        if (ck < 31) {
            storeA((ck + 1) & 1, av);
            storeB((ck + 1) & 1, bv);
            __syncthreads();
        }
    }

    // ---- epilogue ----
    // c0=D[r][2c], c1=D[r][2c+1], c2=D[r+8][2c], c3=D[r+8][2c+1];
    // r = lane>>2 (+mfrag*16), c = lane&3 (+nfrag*8 cols/2)
    const int rbase = lane >> 2;
    const int cpair = (lane & 3) * 2;

    if (MODE == 0) {
        const int sel = n0 >> 10;     // 128-tile never straddles the 1024-col q/k/v split
        float* dstbuf = (sel == 0) ? g_q : (sel == 1) ? g_k : g_v;
#pragma unroll
        for (int im = 0; im < 4; im++) {
            const int mrow = m0 + (wm * 4 + im) * 16 + rbase;
#pragma unroll
            for (int in = 0; in < 4; in++) {
                const int nloc = (wn * 4 + in) * 8 + cpair;
                const int lc = (n0 & 1023) + nloc;
                const int h = lc >> 6;
                const int e = lc & 63;
                const float bx = biasS[nloc], by = biasS[nloc + 1];
#pragma unroll
                for (int rr = 0; rr < 2; rr++) {
                    const int m = mrow + rr * 8;
                    const int b = m >> 9;
                    const int tt = m & 511;
                    float2 v;
                    v.x = acc[im][in][rr * 2 + 0] + bx;
                    v.y = acc[im][in][rr * 2 + 1] + by;
                    *(float2*)&dstbuf[(((size_t)(b * cfg::H + h) * cfg::T) + tt) *
                                          cfg::E + e] = v;
                }
            }
        }
    } else {
#pragma unroll
        for (int im = 0; im < 4; im++) {
            const int mrow = m0 + (wm * 4 + im) * 16 + rbase;
#pragma unroll
            for (int in = 0; in < 4; in++) {
                const int nloc = (wn * 4 + in) * 8 + cpair;
                const float bx = biasS[nloc], by = biasS[nloc + 1];
#pragma unroll
                for (int rr = 0; rr < 2; rr++) {
                    const int m = mrow + rr * 8;
                    float2 v;
                    v.x = acc[im][in][rr * 2 + 0] + bx;
                    v.y = acc[im][in][rr * 2 + 1] + by;
                    *(float2*)&out[(size_t)m * cfg::C + n0 + nloc] = v;
                }
            }
        }
    }
}

// ---------------------------------------------------------------------------
// Flash attention (unchanged known-correct SIMT): block per (q-tile 64, h, b)
// ---------------------------------------------------------------------------
__global__ __launch_bounds__(256) void attn_kernel(const float* __restrict__ kc,
                                                   const float* __restrict__ vc) {
    constexpr int STR = 68;
    extern __shared__ float sm[];
    float* q_s = sm;                 // 64 x STR
    float* k_s = sm + 64 * STR;
    float* v_s = sm + 2 * 64 * STR;
    float* p_s = sm + 3 * 64 * STR;

    const int qt = blockIdx.x;
    const int h = blockIdx.y;
    const int b = blockIdx.z;
    const int tid = threadIdx.x;
    const int qg = tid >> 4;   // 0..15
    const int jg = tid & 15;   // 0..15
    const int i0 = qt * 64;

    const size_t bh = (size_t)b * cfg::H + h;
    const float* qbase = g_q + (bh * cfg::T + i0) * cfg::E;
    const float* kcb = kc + bh * cfg::L * cfg::E;
    const float* vcb = vc + bh * cfg::L * cfg::E;
    const float* knb = g_k + bh * cfg::T * cfg::E;
    const float* vnb = g_v + bh * cfg::T * cfg::E;

#pragma unroll
    for (int r = 0; r < 4; r++) {
        const int fi = r * 256 + tid;
        const int row = fi >> 4;
        const int c4 = (fi & 15) * 4;
        *(float4*)&q_s[row * STR + c4] = *(const float4*)&qbase[row * 64 + c4];
    }

    float m_i[4], l_i[4], accv[4][4];
#pragma unroll
    for (int qi = 0; qi < 4; qi++) {
        m_i[qi] = -CUDART_INF_F;
        l_i[qi] = 0.f;
#pragma unroll
        for (int ei = 0; ei < 4; ei++) accv[qi][ei] = 0.f;
    }

    const int ntiles = cfg::NCT + qt + 1;
    const float scale = 0.125f;  // 1/sqrt(64)

    for (int tIdx = 0; tIdx < ntiles; tIdx++) {
        const float* ksrc;
        const float* vsrc;
        bool diag = false;
        if (tIdx < cfg::NCT) {
            ksrc = kcb + (size_t)tIdx * 64 * cfg::E;
            vsrc = vcb + (size_t)tIdx * 64 * cfg::E;
        } else {
            const int kt = tIdx - cfg::NCT;
            ksrc = knb + (size_t)kt * 64 * cfg::E;
            vsrc = vnb + (size_t)kt * 64 * cfg::E;
            diag = (kt == qt);
        }
        __syncthreads();
#pragma unroll
        for (int r = 0; r < 4; r++) {
            const int fi = r * 256 + tid;
            const int row = fi >> 4;
            const int c4 = (fi & 15) * 4;
            *(float4*)&k_s[row * STR + c4] = *(const float4*)&ksrc[row * 64 + c4];
            *(float4*)&v_s[row * STR + c4] = *(const float4*)&vsrc[row * 64 + c4];
        }
        __syncthreads();

        float s[4][4] = {};
#pragma unroll 2
        for (int e0 = 0; e0 < 64; e0 += 4) {
            float4 qv[4];
#pragma unroll
            for (int qi = 0; qi < 4; qi++)
                qv[qi] = *(const float4*)&q_s[(qg * 4 + qi) * STR + e0];
#pragma unroll
            for (int ji = 0; ji < 4; ji++) {
                const float4 kv = *(const float4*)&k_s[(jg + 16 * ji) * STR + e0];
#pragma unroll
                for (int qi = 0; qi < 4; qi++) {
                    s[qi][ji] += qv[qi].x * kv.x + qv[qi].y * kv.y
                               + qv[qi].z * kv.z + qv[qi].w * kv.w;
                }
            }
        }

#pragma unroll
        for (int qi = 0; qi < 4; qi++) {
            float sr[4];
#pragma unroll
            for (int ji = 0; ji < 4; ji++) {
                float v = s[qi][ji] * scale;
                if (diag && (jg + 16 * ji > qg * 4 + qi)) v = -CUDART_INF_F;
                sr[ji] = v;
            }
            float tm = fmaxf(fmaxf(sr[0], sr[1]), fmaxf(sr[2], sr[3]));
#pragma unroll
            for (int o = 1; o < 16; o <<= 1)
                tm = fmaxf(tm, __shfl_xor_sync(0xffffffffu, tm, o));
            const float mn = fmaxf(m_i[qi], tm);
            const float corr = __expf(m_i[qi] - mn);
            m_i[qi] = mn;
            float ps = 0.f;
#pragma unroll
            for (int ji = 0; ji < 4; ji++) {
                const float p = __expf(sr[ji] - mn);
                ps += p;
                p_s[(qg * 4 + qi) * STR + jg + 16 * ji] = p;
            }
#pragma unroll
            for (int o = 1; o < 16; o <<= 1)
                ps += __shfl_xor_sync(0xffffffffu, ps, o);
            l_i[qi] = l_i[qi] * corr + ps;
#pragma unroll
            for (int ei = 0; ei < 4; ei++) accv[qi][ei] *= corr;
        }
        __syncwarp();

#pragma unroll 4
        for (int j = 0; j < 64; j++) {
            const float4 vv = *(const float4*)&v_s[j * STR + jg * 4];
#pragma unroll
            for (int qi = 0; qi < 4; qi++) {
                const float pj = p_s[(qg * 4 + qi) * STR + j];
                accv[qi][0] += pj * vv.x;
                accv[qi][1] += pj * vv.y;
                accv[qi][2] += pj * vv.z;
                accv[qi][3] += pj * vv.w;
            }
        }
        __syncwarp();
    }

#pragma unroll
    for (int qi = 0; qi < 4; qi++) {
        const float inv = 1.f / l_i[qi];
        float4 o;
        o.x = accv[qi][0] * inv;
        o.y = accv[qi][1] * inv;
        o.z = accv[qi][2] * inv;
        o.w = accv[qi][3] * inv;
        const int trow = i0 + qg * 4 + qi;
        *(float4*)&g_y[((size_t)b * cfg::T + trow) * cfg::C + h * cfg::E + jg * 4] = o;
    }
}

// ---------------------------------------------------------------------------
extern "C" void kernel_launch(void* const* d_in, const int* in_sizes, int n_in,
                              void* d_out, int out_size) {
    const float* x     = (const float*)d_in[0];
    const float* kcch  = (const float*)d_in[1];
    const float* vcch  = (const float*)d_in[2];
    const float* Wqkv  = (const float*)d_in[3];
    const float* bqkv  = (const float*)d_in[4];
    const float* Wproj = (const float*)d_in[5];
    const float* bproj = (const float*)d_in[6];
    float* out = (float*)d_out;

    const int attn_smem = 4 * 64 * 68 * (int)sizeof(float);  // 69632 B
    cudaFuncSetAttribute(attn_kernel, cudaFuncAttributeMaxDynamicSharedMemorySize,
                         attn_smem);
    cudaFuncSetAttribute(gemm_mma<cfg::NQKV, 0>,
                         cudaFuncAttributeMaxDynamicSharedMemorySize, GM_SMEM_BYTES);
    cudaFuncSetAttribute(gemm_mma<cfg::C, 1>,
                         cudaFuncAttributeMaxDynamicSharedMemorySize, GM_SMEM_BYTES);

    // 1) QKV projection + head split (tf32 mma.sync); W used directly (k-major)
    gemm_mma<cfg::NQKV, 0><<<dim3(cfg::NQKV / 128, cfg::M / 128), 256,
                             GM_SMEM_BYTES>>>(x, Wqkv, bqkv, nullptr);

    // 2) Flash attention over cache + new keys
    attn_kernel<<<dim3(cfg::T / 64, cfg::H, cfg::B), 256, attn_smem>>>(kcch, vcch);

    // 3) Output projection (tf32 mma.sync)
    gemm_mma<cfg::C, 1><<<dim3(cfg::C / 128, cfg::M / 128), 256,
                          GM_SMEM_BYTES>>>(nullptr, Wproj, bproj, out);
}

// round 7
// speedup vs baseline: 2.7418x; 2.0521x over previous
#include <cuda_runtime.h>
#include <math_constants.h>
#include <cstdint>
#include <cstddef>

// Problem constants
namespace cfg {
constexpr int B = 8, T = 512, C = 1024, H = 16, E = 64, L = 2048;
constexpr int M = B * T;        // 4096 rows for both GEMMs
constexpr int NQKV = 3 * C;     // 3072
constexpr int NCT = L / 64;     // 32 cache key-tiles
}

// Scratch (device globals — no allocation allowed)
__device__ float g_q[cfg::B * cfg::H * cfg::T * cfg::E];   // (B,H,T,E)
__device__ float g_k[cfg::B * cfg::H * cfg::T * cfg::E];
__device__ float g_v[cfg::B * cfg::H * cfg::T * cfg::E];
__device__ float g_y[cfg::B * cfg::T * cfg::C];            // (B,T,C) attention out

// ---------------------------------------------------------------------------
// mma.sync helpers (portable PTX, works at compute_103 base target)
// ---------------------------------------------------------------------------
__device__ __forceinline__ uint32_t f2tf32(float x) {
    uint32_t r;
    asm("cvt.rna.tf32.f32 %0, %1;" : "=r"(r) : "f"(x));
    return r;
}

// D(16x8,f32) += A(16x8,tf32) * B(8x8,tf32)
__device__ __forceinline__ void mma_tf32(float* d, const uint32_t* a,
                                         const uint32_t* b) {
    asm volatile(
        "mma.sync.aligned.m16n8k8.row.col.f32.tf32.tf32.f32 "
        "{%0,%1,%2,%3}, {%4,%5,%6,%7}, {%8,%9}, {%0,%1,%2,%3};"
        : "+f"(d[0]), "+f"(d[1]), "+f"(d[2]), "+f"(d[3])
        : "r"(a[0]), "r"(a[1]), "r"(a[2]), "r"(a[3]), "r"(b[0]), "r"(b[1]));
}

// ---------------------------------------------------------------------------
// tf32 mma.sync GEMM (validated in R6 — unchanged): 128x128 CTA tile, K=1024.
// ---------------------------------------------------------------------------
constexpr int GM_SMEM_U32 = 8192 + 8192 + 128;
constexpr int GM_SMEM_BYTES = GM_SMEM_U32 * 4;   // 66048

template <int N, int MODE>
__global__ __launch_bounds__(256) void gemm_mma(const float* __restrict__ Ag,
                                                const float* __restrict__ W,
                                                const float* __restrict__ bias,
                                                float* __restrict__ out) {
    extern __shared__ uint32_t sh[];
    float* biasS = (float*)(sh + 16384);

    const int t = threadIdx.x;
    const int lane = t & 31;
    const int wid = t >> 5;
    const int wm = wid >> 2;     // 0..1
    const int wn = wid & 3;      // 0..3
    const int m0 = blockIdx.y * 128;
    const int n0 = blockIdx.x * 128;

    const float* Abase = (MODE == 1) ? g_y : Ag;
    if (t < 128) biasS[t] = bias[n0 + t];

    float acc[4][4][4];
#pragma unroll
    for (int im = 0; im < 4; im++)
#pragma unroll
        for (int in = 0; in < 4; in++)
#pragma unroll
            for (int k = 0; k < 4; k++) acc[im][in][k] = 0.f;

    const int a_row_b = t >> 3;
    const int a_kq = t & 7;
    const int b_kr = t >> 3;
    const int b_nq_b = t & 7;

    auto loadA = [&](int ck, float4* av) {
#pragma unroll
        for (int i = 0; i < 4; i++) {
            const int row = a_row_b + 32 * i;
            av[i] = *(const float4*)(Abase + (size_t)(m0 + row) * cfg::C +
                                     ck * 32 + a_kq * 4);
        }
    };
    auto loadB = [&](int ck, float4* bv) {
#pragma unroll
        for (int i = 0; i < 4; i++) {
            const int nq = b_nq_b + 8 * i;
            bv[i] = *(const float4*)(W + (size_t)(ck * 32 + b_kr) * N + n0 +
                                     nq * 4);
        }
    };
    auto storeA = [&](int buf, const float4* av) {
#pragma unroll
        for (int i = 0; i < 4; i++) {
            const int row = a_row_b + 32 * i;
            const int mf = row >> 4;
            const int r = row & 15;
            const int ks = a_kq >> 1;
            const int slot = ((a_kq & 1) << 1) | (r >> 3);
            const int lb = (r & 7) << 2;
            const float* vv = (const float*)&av[i];
#pragma unroll
            for (int j = 0; j < 4; j++) {
                const int pl = (lb + j) ^ (ks << 2);
                sh[((((buf * 8 + mf) * 4 + ks) * 32 + pl) << 2) + slot] =
                    f2tf32(vv[j]);
            }
        }
    };
    auto storeB = [&](int buf, const float4* bv) {
#pragma unroll
        for (int i = 0; i < 4; i++) {
            const int nq = b_nq_b + 8 * i;
            const int nf = nq >> 1;
            const int ks = b_kr >> 3;
            const int slot = (b_kr >> 2) & 1;
            const int lb = ((nq & 1) << 4) | (b_kr & 3);
            const float* vv = (const float*)&bv[i];
#pragma unroll
            for (int j = 0; j < 4; j++) {
                const int pl = (lb + (j << 2)) ^ ((nf & 3) << 2);
                sh[8192 + ((((buf * 16 + nf) * 4 + ks) * 32 + pl) << 1) + slot] =
                    f2tf32(vv[j]);
            }
        }
    };

    auto compute = [&](int buf) {
#pragma unroll
        for (int ks = 0; ks < 4; ks++) {
            uint32_t a[4][4];
            uint32_t b[4][2];
#pragma unroll
            for (int im = 0; im < 4; im++) {
                const int mf = wm * 4 + im;
                const int pl = lane ^ (ks << 2);
                uint4 v = *(const uint4*)&sh[(((buf * 8 + mf) * 4 + ks) * 32 + pl) << 2];
                a[im][0] = v.x; a[im][1] = v.y; a[im][2] = v.z; a[im][3] = v.w;
            }
#pragma unroll
            for (int in = 0; in < 4; in++) {
                const int nf = wn * 4 + in;
                const int pl = lane ^ ((nf & 3) << 2);
                uint2 v = *(const uint2*)&sh[8192 + ((((buf * 16 + nf) * 4 + ks) * 32 + pl) << 1)];
                b[in][0] = v.x; b[in][1] = v.y;
            }
#pragma unroll
            for (int im = 0; im < 4; im++)
#pragma unroll
                for (int in = 0; in < 4; in++)
                    mma_tf32(acc[im][in], a[im], b[in]);
        }
    };

    {
        float4 av[4], bv[4];
        loadA(0, av); loadB(0, bv);
        storeA(0, av); storeB(0, bv);
    }
    __syncthreads();
    for (int ck = 0; ck < 32; ck++) {
        float4 av[4], bv[4];
        if (ck < 31) { loadA(ck + 1, av); loadB(ck + 1, bv); }
        compute(ck & 1);
        if (ck < 31) {
            storeA((ck + 1) & 1, av);
            storeB((ck + 1) & 1, bv);
            __syncthreads();
        }
    }

    const int rbase = lane >> 2;
    const int cpair = (lane & 3) * 2;

    if (MODE == 0) {
        const int sel = n0 >> 10;
        float* dstbuf = (sel == 0) ? g_q : (sel == 1) ? g_k : g_v;
#pragma unroll
        for (int im = 0; im < 4; im++) {
            const int mrow = m0 + (wm * 4 + im) * 16 + rbase;
#pragma unroll
            for (int in = 0; in < 4; in++) {
                const int nloc = (wn * 4 + in) * 8 + cpair;
                const int lc = (n0 & 1023) + nloc;
                const int h = lc >> 6;
                const int e = lc & 63;
                const float bx = biasS[nloc], by = biasS[nloc + 1];
#pragma unroll
                for (int rr = 0; rr < 2; rr++) {
                    const int m = mrow + rr * 8;
                    const int b = m >> 9;
                    const int tt = m & 511;
                    float2 v;
                    v.x = acc[im][in][rr * 2 + 0] + bx;
                    v.y = acc[im][in][rr * 2 + 1] + by;
                    *(float2*)&dstbuf[(((size_t)(b * cfg::H + h) * cfg::T) + tt) *
                                          cfg::E + e] = v;
                }
            }
        }
    } else {
#pragma unroll
        for (int im = 0; im < 4; im++) {
            const int mrow = m0 + (wm * 4 + im) * 16 + rbase;
#pragma unroll
            for (int in = 0; in < 4; in++) {
                const int nloc = (wn * 4 + in) * 8 + cpair;
                const float bx = biasS[nloc], by = biasS[nloc + 1];
#pragma unroll
                for (int rr = 0; rr < 2; rr++) {
                    const int m = mrow + rr * 8;
                    float2 v;
                    v.x = acc[im][in][rr * 2 + 0] + bx;
                    v.y = acc[im][in][rr * 2 + 1] + by;
                    *(float2*)&out[(size_t)m * cfg::C + n0 + nloc] = v;
                }
            }
        }
    }
}

// ---------------------------------------------------------------------------
// Flash attention on mma.sync tf32.
// CTA = (q-tile of 128 rows, head, batch); 256 threads = 8 warps; warp w owns
// query rows w*16..w*16+15. Per 64-key tile: QK^T (64 mma), online softmax in
// fragments, P -> smem (A-frag order), PV (64 mma) into O accumulator.
//
// SMEM (u32 idx):
//   Qf [mf8][ks8][lane32][slot4]           0      (8192)  A-frag order, tf32
//   Kf [nf8][ks8][lane32][slot2]           8192   (4096)  B-frag (n=key,k=e)
//   Vf [nf8][ks8][lane32][slot2]           12288  (4096)  B-frag (n=e,k=key)
//   Pf [mf8][ks8][slot4][lane32]           16384  (8192)  A-frag (k=key)
// Swizzles: Qf/Pf lane^(ks<<2); Kf/Vf lane^(((nf&3)<<2)|((ks&1)<<1)).
// ---------------------------------------------------------------------------
constexpr int AT_QF = 0;
constexpr int AT_KF = 8192;
constexpr int AT_VF = 12288;
constexpr int AT_PF = 16384;
constexpr int AT_SMEM_BYTES = 24576 * 4;   // 98304

__global__ __launch_bounds__(256, 2) void attn_mma(const float* __restrict__ kc,
                                                   const float* __restrict__ vc) {
    extern __shared__ uint32_t sh[];
    const int t = threadIdx.x;
    const int lane = t & 31;
    const int w = t >> 5;
    const int qt = blockIdx.x;
    const int h = blockIdx.y;
    const int b = blockIdx.z;
    const int i0 = qt * 128;

    const size_t bh = (size_t)b * cfg::H + h;
    const float* qb = g_q + (bh * cfg::T + i0) * 64;
    const float* kcb = kc + bh * cfg::L * 64;
    const float* vcb = vc + bh * cfg::L * 64;
    const float* knb = g_k + bh * cfg::T * 64;
    const float* vnb = g_v + bh * cfg::T * 64;

    // ---- load Q (128x64) into Qf, convert to tf32, A-frag order ----
    {
        const int row_b = t >> 2;        // + 64*i2
        const int eqb = (t & 3) * 4;     // + 16*k4 + j
#pragma unroll
        for (int i2 = 0; i2 < 2; i2++) {
            const int row = row_b + 64 * i2;
            const int mf = row >> 4;
            const int r = row & 15;
            const int lb = (r & 7) << 2;
            const int rhi = (r >> 3) & 1;
#pragma unroll
            for (int k4 = 0; k4 < 4; k4++) {
                const float4 v = *(const float4*)(qb + (size_t)row * 64 + eqb + 16 * k4);
                const float* vv = (const float*)&v;
#pragma unroll
                for (int j = 0; j < 4; j++) {
                    const int e = eqb + 16 * k4 + j;
                    const int ks = e >> 3;
                    const int slot = (((e & 7) >= 4) ? 2 : 0) | rhi;
                    const int pl = (lb | (e & 3)) ^ (ks << 2);
                    sh[AT_QF + ((mf * 8 + ks) * 32 + pl) * 4 + slot] = f2tf32(vv[j]);
                }
            }
        }
    }

    float o[8][4];
#pragma unroll
    for (int nf = 0; nf < 8; nf++)
#pragma unroll
        for (int r = 0; r < 4; r++) o[nf][r] = 0.f;
    float mA = -CUDART_INF_F, mB = -CUDART_INF_F, lA = 0.f, lB = 0.f;

    // K/V loader indices: thread covers one key row, 4 float4 along e
    const int key = t >> 2;
    const int e0b = (t & 3) * 4;
    const int knf = key >> 3;          // K: n-frag;  V: ks
    const int k7 = key & 7;
    const int k3 = key & 3;
    const int vslot = k7 >> 2;

    const int ntiles = 34 + 2 * qt;
    const float scale = 0.125f;        // 1/sqrt(64)

    for (int ti = 0; ti < ntiles; ti++) {
        const float* ksrc;
        const float* vsrc;
        if (ti < cfg::NCT) {
            ksrc = kcb + (size_t)ti * 64 * 64;
            vsrc = vcb + (size_t)ti * 64 * 64;
        } else {
            const int kt = ti - cfg::NCT;
            ksrc = knb + (size_t)kt * 64 * 64;
            vsrc = vnb + (size_t)kt * 64 * 64;
        }
        __syncthreads();   // Kf/Vf free (previous tile's compute done)

        // ---- load + convert K,V tile into frag-order smem ----
#pragma unroll
        for (int k4 = 0; k4 < 4; k4++) {
            const float4 kv = *(const float4*)(ksrc + (size_t)key * 64 + e0b + 16 * k4);
            const float4 vv = *(const float4*)(vsrc + (size_t)key * 64 + e0b + 16 * k4);
            const float* kp = (const float*)&kv;
            const float* vp = (const float*)&vv;
#pragma unroll
            for (int j = 0; j < 4; j++) {
                const int e = e0b + 16 * k4 + j;
                // K as B (n=key, k=e)
                {
                    const int ks2 = e >> 3;
                    const int slot = (e & 7) >> 2;
                    const int pl = ((k7 << 2) | (e & 3)) ^
                                   (((knf & 3) << 2) | ((ks2 & 1) << 1));
                    sh[AT_KF + ((knf * 8 + ks2) * 32 + pl) * 2 + slot] = f2tf32(kp[j]);
                }
                // V as B (n=e, k=key)
                {
                    const int nf2 = e >> 3;
                    const int pl = (((e & 7) << 2) | k3) ^
                                   (((nf2 & 3) << 2) | ((knf & 1) << 1));
                    sh[AT_VF + ((nf2 * 8 + knf) * 32 + pl) * 2 + vslot] = f2tf32(vp[j]);
                }
            }
        }
        __syncthreads();

        // ---- S = Q @ K^T ----
        float s[8][4];
#pragma unroll
        for (int nf = 0; nf < 8; nf++)
#pragma unroll
            for (int r = 0; r < 4; r++) s[nf][r] = 0.f;
#pragma unroll
        for (int ks = 0; ks < 8; ks++) {
            uint32_t a[4];
            const uint4 av = *(const uint4*)&sh[AT_QF + ((w * 8 + ks) * 32 +
                                                         (lane ^ (ks << 2))) * 4];
            a[0] = av.x; a[1] = av.y; a[2] = av.z; a[3] = av.w;
#pragma unroll
            for (int nf = 0; nf < 8; nf++) {
                const uint2 bv = *(const uint2*)&sh[AT_KF + ((nf * 8 + ks) * 32 +
                    (lane ^ (((nf & 3) << 2) | ((ks & 1) << 1)))) * 2];
                uint32_t bb[2] = {bv.x, bv.y};
                mma_tf32(s[nf], a, bb);
            }
        }

        // ---- online softmax ----
        const bool diag = (ti >= cfg::NCT + 2 * qt);
        const int rowA = i0 + w * 16 + (lane >> 2);
        const int colb = (ti - cfg::NCT) * 64 + 2 * (lane & 3);
        float mxA = -CUDART_INF_F, mxB = -CUDART_INF_F;
#pragma unroll
        for (int nf = 0; nf < 8; nf++) {
#pragma unroll
            for (int r = 0; r < 4; r++) s[nf][r] *= scale;
            if (diag) {
                const int c0 = colb + nf * 8;
                if (c0 > rowA) s[nf][0] = -CUDART_INF_F;
                if (c0 + 1 > rowA) s[nf][1] = -CUDART_INF_F;
                if (c0 > rowA + 8) s[nf][2] = -CUDART_INF_F;
                if (c0 + 1 > rowA + 8) s[nf][3] = -CUDART_INF_F;
            }
            mxA = fmaxf(mxA, fmaxf(s[nf][0], s[nf][1]));
            mxB = fmaxf(mxB, fmaxf(s[nf][2], s[nf][3]));
        }
        mxA = fmaxf(mxA, __shfl_xor_sync(0xffffffffu, mxA, 1));
        mxA = fmaxf(mxA, __shfl_xor_sync(0xffffffffu, mxA, 2));
        mxB = fmaxf(mxB, __shfl_xor_sync(0xffffffffu, mxB, 1));
        mxB = fmaxf(mxB, __shfl_xor_sync(0xffffffffu, mxB, 2));

        const float mAn = fmaxf(mA, mxA);
        const float mBn = fmaxf(mB, mxB);
        const float cA = __expf(mA - mAn);
        const float cB = __expf(mB - mBn);
        mA = mAn; mB = mBn;

        float sA = 0.f, sB = 0.f;
#pragma unroll
        for (int nf = 0; nf < 8; nf++) {
            s[nf][0] = __expf(s[nf][0] - mA); sA += s[nf][0];
            s[nf][1] = __expf(s[nf][1] - mA); sA += s[nf][1];
            s[nf][2] = __expf(s[nf][2] - mB); sB += s[nf][2];
            s[nf][3] = __expf(s[nf][3] - mB); sB += s[nf][3];
        }
        sA += __shfl_xor_sync(0xffffffffu, sA, 1);
        sA += __shfl_xor_sync(0xffffffffu, sA, 2);
        sB += __shfl_xor_sync(0xffffffffu, sB, 1);
        sB += __shfl_xor_sync(0xffffffffu, sB, 2);
        lA = lA * cA + sA;
        lB = lB * cB + sB;
#pragma unroll
        for (int nf = 0; nf < 8; nf++) {
            o[nf][0] *= cA; o[nf][1] *= cA;
            o[nf][2] *= cB; o[nf][3] *= cB;
        }

        // ---- P -> Pf (A-frag order, k = key) ----
        {
            const int pr = lane >> 2;
            const int pc = lane & 3;
#pragma unroll
            for (int nf = 0; nf < 8; nf++) {
#pragma unroll
                for (int r = 0; r < 4; r++) {
                    const int d = r & 1;
                    const int slot = ((pc >= 2) ? 2 : 0) | (r >> 1);
                    const int pl = ((pr << 2) | ((2 * (pc & 1)) + d)) ^ (nf << 2);
                    sh[AT_PF + ((w * 8 + nf) * 4 + slot) * 32 + pl] = f2tf32(s[nf][r]);
                }
            }
        }
        __syncwarp();

        // ---- O += P @ V ----
#pragma unroll
        for (int ks = 0; ks < 8; ks++) {
            uint32_t a[4];
            const int pla = lane ^ (ks << 2);
#pragma unroll
            for (int si = 0; si < 4; si++)
                a[si] = sh[AT_PF + ((w * 8 + ks) * 4 + si) * 32 + pla];
#pragma unroll
            for (int nf = 0; nf < 8; nf++) {
                const uint2 bv = *(const uint2*)&sh[AT_VF + ((nf * 8 + ks) * 32 +
                    (lane ^ (((nf & 3) << 2) | ((ks & 1) << 1)))) * 2];
                uint32_t bb[2] = {bv.x, bv.y};
                mma_tf32(o[nf], a, bb);
            }
        }
    }

    // ---- epilogue: y = O / l -> g_y[b, t, h*64 + e] ----
    const float iA = 1.f / lA;
    const float iB = 1.f / lB;
    const int trA = i0 + w * 16 + (lane >> 2);
    const int ec = 2 * (lane & 3);
#pragma unroll
    for (int nf = 0; nf < 8; nf++) {
        const int e = nf * 8 + ec;
        float2 vA, vB;
        vA.x = o[nf][0] * iA; vA.y = o[nf][1] * iA;
        vB.x = o[nf][2] * iB; vB.y = o[nf][3] * iB;
        *(float2*)&g_y[((size_t)b * cfg::T + trA) * cfg::C + h * 64 + e] = vA;
        *(float2*)&g_y[((size_t)b * cfg::T + trA + 8) * cfg::C + h * 64 + e] = vB;
    }
}

// ---------------------------------------------------------------------------
extern "C" void kernel_launch(void* const* d_in, const int* in_sizes, int n_in,
                              void* d_out, int out_size) {
    const float* x     = (const float*)d_in[0];
    const float* kcch  = (const float*)d_in[1];
    const float* vcch  = (const float*)d_in[2];
    const float* Wqkv  = (const float*)d_in[3];
    const float* bqkv  = (const float*)d_in[4];
    const float* Wproj = (const float*)d_in[5];
    const float* bproj = (const float*)d_in[6];
    float* out = (float*)d_out;

    cudaFuncSetAttribute(attn_mma, cudaFuncAttributeMaxDynamicSharedMemorySize,
                         AT_SMEM_BYTES);
    cudaFuncSetAttribute(gemm_mma<cfg::NQKV, 0>,
                         cudaFuncAttributeMaxDynamicSharedMemorySize, GM_SMEM_BYTES);
    cudaFuncSetAttribute(gemm_mma<cfg::C, 1>,
                         cudaFuncAttributeMaxDynamicSharedMemorySize, GM_SMEM_BYTES);

    // 1) QKV projection + head split (tf32 mma.sync)
    gemm_mma<cfg::NQKV, 0><<<dim3(cfg::NQKV / 128, cfg::M / 128), 256,
                             GM_SMEM_BYTES>>>(x, Wqkv, bqkv, nullptr);

    // 2) Flash attention (tf32 mma.sync)
    attn_mma<<<dim3(cfg::T / 128, cfg::H, cfg::B), 256, AT_SMEM_BYTES>>>(kcch, vcch);

    // 3) Output projection (tf32 mma.sync)
    gemm_mma<cfg::C, 1><<<dim3(cfg::C / 128, cfg::M / 128), 256,
                          GM_SMEM_BYTES>>>(nullptr, Wproj, bproj, out);
}

// round 8
// speedup vs baseline: 5.3693x; 1.9583x over previous
#include <cuda_runtime.h>
#include <cuda_fp16.h>
#include <math_constants.h>
#include <cstdint>
#include <cstddef>

// Problem constants
namespace cfg {
constexpr int B = 8, T = 512, C = 1024, H = 16, E = 64, L = 2048;
constexpr int M = B * T;        // 4096 rows for both GEMMs
constexpr int NQKV = 3 * C;     // 3072
constexpr int NCT = L / 64;     // 32 cache key-tiles
}

// Scratch (device globals — no allocation allowed)
__device__ float g_q[cfg::B * cfg::H * cfg::T * cfg::E];   // (B,H,T,E)
__device__ float g_k[cfg::B * cfg::H * cfg::T * cfg::E];
__device__ float g_v[cfg::B * cfg::H * cfg::T * cfg::E];
__device__ float g_y[cfg::B * cfg::T * cfg::C];            // (B,T,C) attention out

// ---------------------------------------------------------------------------
// fp16 mma.sync helpers (portable PTX, sm_80+, fine at compute_103 base)
// ---------------------------------------------------------------------------
__device__ __forceinline__ uint32_t packh2(float lo, float hi) {
    __half2 h = __floats2half2_rn(lo, hi);   // lo -> low 16 bits
    return *(uint32_t*)&h;
}

// D(16x8,f32) += A(16x16,f16) * B(16x8,f16)
__device__ __forceinline__ void mma_f16(float* d, const uint32_t* a,
                                        const uint32_t* b) {
    asm volatile(
        "mma.sync.aligned.m16n8k16.row.col.f32.f16.f16.f32 "
        "{%0,%1,%2,%3}, {%4,%5,%6,%7}, {%8,%9}, {%0,%1,%2,%3};"
        : "+f"(d[0]), "+f"(d[1]), "+f"(d[2]), "+f"(d[3])
        : "r"(a[0]), "r"(a[1]), "r"(a[2]), "r"(a[3]), "r"(b[0]), "r"(b[1]));
}

// ---------------------------------------------------------------------------
// fp16 mma GEMM: 128x128 CTA tile, K=1024 in chunks of 32, double-buffered
// fragment-order SMEM (half2 packed). 256 threads = 8 warps (2m x 4n),
// warp tile 64x32 = 4x4 frags of m16n8k16 (2 k-steps per chunk).
// MODE 0: out = X @ Wqkv + b   -> scattered into g_q/g_k/g_v as (B,H,T,E)
// MODE 1: out = g_y @ Wproj + b -> dense `out`
//
// SMEM u32 layout per buffer (buf stride 4096):
//   Af[mf8][ks2][pl32][slot4]  @ buf*4096        (2048)
//   Bf[nf16][ks2][pl32][slot2] @ buf*4096 + 2048 (2048)
//   bias[128] @ 8192
// A: pl = ((r&7)<<2)|c (no swizzle). B: pl = raw ^ SB(nf),
//   SB(nf) = ((nf&3)<<2) | (((nf>>2)&1)<<1).
// ---------------------------------------------------------------------------
constexpr int GM_SMEM_U32 = 8192 + 128;
constexpr int GM_SMEM_BYTES = GM_SMEM_U32 * 4;   // 33280

template <int N, int MODE>
__global__ __launch_bounds__(256) void gemm_mma(const float* __restrict__ Ag,
                                                const float* __restrict__ W,
                                                const float* __restrict__ bias,
                                                float* __restrict__ out) {
    extern __shared__ uint32_t sh[];
    float* biasS = (float*)(sh + 8192);

    const int t = threadIdx.x;
    const int lane = t & 31;
    const int wid = t >> 5;
    const int wm = wid >> 2;     // 0..1
    const int wn = wid & 3;      // 0..3
    const int m0 = blockIdx.y * 128;
    const int n0 = blockIdx.x * 128;

    const float* Abase = (MODE == 1) ? g_y : Ag;
    if (t < 128) biasS[t] = bias[n0 + t];

    float acc[4][4][4];
#pragma unroll
    for (int im = 0; im < 4; im++)
#pragma unroll
        for (int in = 0; in < 4; in++)
#pragma unroll
            for (int k = 0; k < 4; k++) acc[im][in][k] = 0.f;

    // ---- A loader/storer mapping ----
    // thread: rows row0+32*i (i=0..3), k-float4 kq = t&7
    const int row0 = t >> 3;
    const int kq = t & 7;
    const uint32_t abase =
        (uint32_t)((((row0 >> 4) * 2 + (kq >> 2)) * 32 +
                    (((row0 & 7) << 2) | (2 * (t & 1)))) * 4 +
                   (((t & 2) ? 2 : 0) | ((row0 >> 3) & 1)));
    // idx(i,h) = abase + i*512 + h*4

    // ---- B loader/storer mapping ----
    // thread: k-pair kp = t>>4 (rows 2kp,2kp+1), n-float4 nq0 = t&15 (+16*i2)
    const int kp = t >> 4;
    const int nq0 = t & 15;
    const int nf0 = nq0 >> 1;
    const int bm = nf0 & 3;                       // j XOR mask
    const uint32_t bbase =
        (uint32_t)((nf0 * 2 + (kp >> 3)) * 64 + ((4 * (nq0 & 1)) << 3) +
                   ((kp & 3) ^ (((nf0 >> 2) & 1) << 1)) * 2 +
                   ((kp & 4) ? 1 : 0));
    // idx(i2,j) = bbase + i2*1024 + ((j^bm)<<3)

    const float* aptr = Abase + (size_t)(m0 + row0) * cfg::C + kq * 4;
    const float* bptr = W + (size_t)(2 * kp) * N + n0 + nq0 * 4;

    auto loadA = [&](int ck, float4* av) {
#pragma unroll
        for (int i = 0; i < 4; i++)
            av[i] = *(const float4*)(aptr + (size_t)(32 * i) * cfg::C + ck * 32);
    };
    auto loadB = [&](int ck, float4* bv) {
#pragma unroll
        for (int i2 = 0; i2 < 2; i2++) {
            const float* p = bptr + (size_t)(ck * 32) * N + 64 * i2;
            bv[2 * i2] = *(const float4*)p;
            bv[2 * i2 + 1] = *(const float4*)(p + N);
        }
    };
    auto storeA = [&](int buf, const float4* av) {
        uint32_t* dst = sh + buf * 4096;
#pragma unroll
        for (int i = 0; i < 4; i++) {
            const float* vv = (const float*)&av[i];
#pragma unroll
            for (int hh = 0; hh < 2; hh++)
                dst[abase + i * 512 + hh * 4] = packh2(vv[2 * hh], vv[2 * hh + 1]);
        }
    };
    auto storeB = [&](int buf, const float4* bv) {
        uint32_t* dst = sh + buf * 4096 + 2048;
#pragma unroll
        for (int i2 = 0; i2 < 2; i2++) {
            const float* lo = (const float*)&bv[2 * i2];
            const float* hi = (const float*)&bv[2 * i2 + 1];
#pragma unroll
            for (int j = 0; j < 4; j++)
                dst[bbase + i2 * 1024 + ((j ^ bm) << 3)] = packh2(lo[j], hi[j]);
        }
    };

    auto compute = [&](int buf) {
        const uint32_t* As = sh + buf * 4096;
        const uint32_t* Bs = sh + buf * 4096 + 2048;
#pragma unroll
        for (int ks = 0; ks < 2; ks++) {
            uint32_t a[4][4];
            uint32_t b[4][2];
#pragma unroll
            for (int im = 0; im < 4; im++) {
                const int mf = wm * 4 + im;
                uint4 v = *(const uint4*)&As[(mf * 2 + ks) * 128 + lane * 4];
                a[im][0] = v.x; a[im][1] = v.y; a[im][2] = v.z; a[im][3] = v.w;
            }
#pragma unroll
            for (int in = 0; in < 4; in++) {
                const int nf = wn * 4 + in;
                const int pl = lane ^ (((nf & 3) << 2) | (((nf >> 2) & 1) << 1));
                uint2 v = *(const uint2*)&Bs[(nf * 2 + ks) * 64 + pl * 2];
                b[in][0] = v.x; b[in][1] = v.y;
            }
#pragma unroll
            for (int im = 0; im < 4; im++)
#pragma unroll
                for (int in = 0; in < 4; in++)
                    mma_f16(acc[im][in], a[im], b[in]);
        }
    };

    {
        float4 av[4], bv[4];
        loadA(0, av); loadB(0, bv);
        storeA(0, av); storeB(0, bv);
    }
    __syncthreads();
    for (int ck = 0; ck < 32; ck++) {
        float4 av[4], bv[4];
        if (ck < 31) { loadA(ck + 1, av); loadB(ck + 1, bv); }
        compute(ck & 1);
        if (ck < 31) {
            storeA((ck + 1) & 1, av);
            storeB((ck + 1) & 1, bv);
            __syncthreads();
        }
    }

    // ---- epilogue (D frag layout same as m16n8k8) ----
    const int rbase = lane >> 2;
    const int cpair = (lane & 3) * 2;

    if (MODE == 0) {
        const int sel = n0 >> 10;
        float* dstbuf = (sel == 0) ? g_q : (sel == 1) ? g_k : g_v;
#pragma unroll
        for (int im = 0; im < 4; im++) {
            const int mrow = m0 + (wm * 4 + im) * 16 + rbase;
#pragma unroll
            for (int in = 0; in < 4; in++) {
                const int nloc = (wn * 4 + in) * 8 + cpair;
                const int lc = (n0 & 1023) + nloc;
                const int h = lc >> 6;
                const int e = lc & 63;
                const float bx = biasS[nloc], by = biasS[nloc + 1];
#pragma unroll
                for (int rr = 0; rr < 2; rr++) {
                    const int m = mrow + rr * 8;
                    const int b = m >> 9;
                    const int tt = m & 511;
                    float2 v;
                    v.x = acc[im][in][rr * 2 + 0] + bx;
                    v.y = acc[im][in][rr * 2 + 1] + by;
                    *(float2*)&dstbuf[(((size_t)(b * cfg::H + h) * cfg::T) + tt) *
                                          cfg::E + e] = v;
                }
            }
        }
    } else {
#pragma unroll
        for (int im = 0; im < 4; im++) {
            const int mrow = m0 + (wm * 4 + im) * 16 + rbase;
#pragma unroll
            for (int in = 0; in < 4; in++) {
                const int nloc = (wn * 4 + in) * 8 + cpair;
                const float bx = biasS[nloc], by = biasS[nloc + 1];
#pragma unroll
                for (int rr = 0; rr < 2; rr++) {
                    const int m = mrow + rr * 8;
                    float2 v;
                    v.x = acc[im][in][rr * 2 + 0] + bx;
                    v.y = acc[im][in][rr * 2 + 1] + by;
                    *(float2*)&out[(size_t)m * cfg::C + n0 + nloc] = v;
                }
            }
        }
    }
}

// ---------------------------------------------------------------------------
// Flash attention, fp16 m16n8k16.
// CTA = (q-tile 128 rows, head, batch); 8 warps; warp w owns rows w*16..+15.
// Q fragments live in registers (16 u32/thread, scale folded in).
// P fragments = register packs of S fragments (no smem round-trip).
// K/V tiles in double-buffered fragment-order smem; one sync per tile.
//
// SMEM u32 (per buffer, buf stride 4096):
//   Kf[nf8][ksK4][pl32][slot2] @ buf*4096          (2048)  n=key, k=e
//   Vf[nf8][ksV4][pl32][slot2] @ buf*4096 + 2048   (2048)  n=e, k=key
// K: pl = ((key&7)<<2)|c (no swizzle). V: pl = raw ^ ((nf&3)<<2).
// ---------------------------------------------------------------------------
constexpr int AT_SMEM_BYTES = 8192 * 4;   // 32768

__global__ __launch_bounds__(256, 2) void attn_mma(const float* __restrict__ kc,
                                                   const float* __restrict__ vc) {
    extern __shared__ uint32_t sh[];
    const int t = threadIdx.x;
    const int lane = t & 31;
    const int w = t >> 5;
    const int qt = blockIdx.x;
    const int h = blockIdx.y;
    const int b = blockIdx.z;
    const int i0 = qt * 128;

    const size_t bh = (size_t)b * cfg::H + h;
    const float* qb = g_q + (bh * cfg::T + i0) * 64;
    const float* kcb = kc + bh * cfg::L * 64;
    const float* vcb = vc + bh * cfg::L * 64;
    const float* knb = g_k + bh * cfg::T * 64;
    const float* vnb = g_v + bh * cfg::T * 64;

    // ---- Q fragments in registers, scale folded ----
    uint32_t qf[4][4];
    {
        const float scale = 0.125f;  // 1/sqrt(64)
        const int r = w * 16 + (lane >> 2);
        const int c2 = 2 * (lane & 3);
        const float* q0 = qb + (size_t)r * 64 + c2;
        const float* q8 = qb + (size_t)(r + 8) * 64 + c2;
#pragma unroll
        for (int ks = 0; ks < 4; ks++) {
            float2 x0 = *(const float2*)(q0 + 16 * ks);
            float2 x1 = *(const float2*)(q8 + 16 * ks);
            float2 x2 = *(const float2*)(q0 + 16 * ks + 8);
            float2 x3 = *(const float2*)(q8 + 16 * ks + 8);
            qf[ks][0] = packh2(x0.x * scale, x0.y * scale);
            qf[ks][1] = packh2(x1.x * scale, x1.y * scale);
            qf[ks][2] = packh2(x2.x * scale, x2.y * scale);
            qf[ks][3] = packh2(x3.x * scale, x3.y * scale);
        }
    }

    // ---- K loader mapping: key = t>>2, e-float4 iters k4 ----
    const int key = t >> 2;
    const int keoff = key * 64 + 4 * (t & 3);     // gmem float offset (+16*k4)
    const uint32_t kbase =
        (uint32_t)((key >> 3) * 256 +
                   ((((key & 7) << 2) | (2 * (t & 1))) * 2) + ((t & 2) ? 1 : 0));
    // idx(k4,h) = kbase + k4*64 + h*2

    // ---- V loader mapping: key-pair kp = t>>3, e-float4 (t&7)+8*i2 ----
    const int kp = t >> 3;
    const int vm = (t >> 1) & 3;                   // nf&3 XOR mask for j
    const uint32_t vbase =
        (uint32_t)((((t & 7) >> 1) * 4 + (kp >> 3)) * 64 +
                   ((4 * (t & 1)) << 3) + (kp & 3) * 2 + ((kp & 4) ? 1 : 0));
    // idx(i2,j) = vbase + i2*1024 + ((j^vm)<<3)
    const int voff = 2 * kp * 64 + 4 * (t & 7);    // gmem (+32*i2; rows +64)

    float o[8][4];
#pragma unroll
    for (int nf = 0; nf < 8; nf++)
#pragma unroll
        for (int r = 0; r < 4; r++) o[nf][r] = 0.f;
    float mA = -CUDART_INF_F, mB = -CUDART_INF_F, lA = 0.f, lB = 0.f;

    const int ntiles = 34 + 2 * qt;

    auto tile_ptrs = [&](int ti, const float*& ks_, const float*& vs_) {
        if (ti < cfg::NCT) {
            ks_ = kcb + (size_t)ti * 4096;
            vs_ = vcb + (size_t)ti * 4096;
        } else {
            ks_ = knb + (size_t)(ti - cfg::NCT) * 4096;
            vs_ = vnb + (size_t)(ti - cfg::NCT) * 4096;
        }
    };
    auto load_kv = [&](const float* ks_, const float* vs_, float4* kpre,
                       float4* vpre) {
#pragma unroll
        for (int k4 = 0; k4 < 4; k4++)
            kpre[k4] = *(const float4*)(ks_ + keoff + 16 * k4);
#pragma unroll
        for (int i2 = 0; i2 < 2; i2++) {
            vpre[2 * i2] = *(const float4*)(vs_ + voff + 32 * i2);
            vpre[2 * i2 + 1] = *(const float4*)(vs_ + voff + 32 * i2 + 64);
        }
    };
    auto store_kv = [&](int buf, const float4* kpre, const float4* vpre) {
        uint32_t* kd = sh + buf * 4096;
        uint32_t* vd = sh + buf * 4096 + 2048;
#pragma unroll
        for (int k4 = 0; k4 < 4; k4++) {
            const float* vv = (const float*)&kpre[k4];
#pragma unroll
            for (int hh = 0; hh < 2; hh++)
                kd[kbase + k4 * 64 + hh * 2] = packh2(vv[2 * hh], vv[2 * hh + 1]);
        }
#pragma unroll
        for (int i2 = 0; i2 < 2; i2++) {
            const float* lo = (const float*)&vpre[2 * i2];
            const float* hi = (const float*)&vpre[2 * i2 + 1];
#pragma unroll
            for (int j = 0; j < 4; j++)
                vd[vbase + i2 * 1024 + ((j ^ vm) << 3)] = packh2(lo[j], hi[j]);
        }
    };

    // preload tile 0 -> buf 0
    {
        const float *ks_, *vs_;
        tile_ptrs(0, ks_, vs_);
        float4 kpre[4], vpre[4];
        load_kv(ks_, vs_, kpre, vpre);
        store_kv(0, kpre, vpre);
    }
    __syncthreads();

    for (int ti = 0; ti < ntiles; ti++) {
        const int cur = (ti & 1) * 4096;
        const uint32_t* Ks = sh + cur;
        const uint32_t* Vs = sh + cur + 2048;

        // prefetch next tile into registers
        float4 kpre[4], vpre[4];
        const bool more = (ti + 1 < ntiles);
        if (more) {
            const float *ks_, *vs_;
            tile_ptrs(ti + 1, ks_, vs_);
            load_kv(ks_, vs_, kpre, vpre);
        }

        // ---- S = Q @ K^T ----
        float s[8][4];
#pragma unroll
        for (int nf = 0; nf < 8; nf++)
#pragma unroll
            for (int r = 0; r < 4; r++) s[nf][r] = 0.f;
#pragma unroll
        for (int ks = 0; ks < 4; ks++) {
#pragma unroll
            for (int nf = 0; nf < 8; nf++) {
                uint2 v = *(const uint2*)&Ks[(nf * 4 + ks) * 64 + lane * 2];
                uint32_t bb[2] = {v.x, v.y};
                mma_f16(s[nf], qf[ks], bb);
            }
        }

        // ---- online softmax (scale already folded into Q) ----
        const bool diag = (ti >= cfg::NCT + 2 * qt);
        const int rowA = i0 + w * 16 + (lane >> 2);
        const int colb = (ti - cfg::NCT) * 64 + 2 * (lane & 3);
        float mxA = -CUDART_INF_F, mxB = -CUDART_INF_F;
#pragma unroll
        for (int nf = 0; nf < 8; nf++) {
            if (diag) {
                const int c0 = colb + nf * 8;
                if (c0 > rowA) s[nf][0] = -CUDART_INF_F;
                if (c0 + 1 > rowA) s[nf][1] = -CUDART_INF_F;
                if (c0 > rowA + 8) s[nf][2] = -CUDART_INF_F;
                if (c0 + 1 > rowA + 8) s[nf][3] = -CUDART_INF_F;
            }
            mxA = fmaxf(mxA, fmaxf(s[nf][0], s[nf][1]));
            mxB = fmaxf(mxB, fmaxf(s[nf][2], s[nf][3]));
        }
        mxA = fmaxf(mxA, __shfl_xor_sync(0xffffffffu, mxA, 1));
        mxA = fmaxf(mxA, __shfl_xor_sync(0xffffffffu, mxA, 2));
        mxB = fmaxf(mxB, __shfl_xor_sync(0xffffffffu, mxB, 1));
        mxB = fmaxf(mxB, __shfl_xor_sync(0xffffffffu, mxB, 2));

        const float mAn = fmaxf(mA, mxA);
        const float mBn = fmaxf(mB, mxB);
        const float cA = __expf(mA - mAn);
        const float cB = __expf(mB - mBn);
        mA = mAn; mB = mBn;

        float sA = 0.f, sB = 0.f;
#pragma unroll
        for (int nf = 0; nf < 8; nf++) {
            s[nf][0] = __expf(s[nf][0] - mA); sA += s[nf][0];
            s[nf][1] = __expf(s[nf][1] - mA); sA += s[nf][1];
            s[nf][2] = __expf(s[nf][2] - mB); sB += s[nf][2];
            s[nf][3] = __expf(s[nf][3] - mB); sB += s[nf][3];
        }
        sA += __shfl_xor_sync(0xffffffffu, sA, 1);
        sA += __shfl_xor_sync(0xffffffffu, sA, 2);
        sB += __shfl_xor_sync(0xffffffffu, sB, 1);
        sB += __shfl_xor_sync(0xffffffffu, sB, 2);
        lA = lA * cA + sA;
        lB = lB * cB + sB;
#pragma unroll
        for (int nf = 0; nf < 8; nf++) {
            o[nf][0] *= cA; o[nf][1] *= cA;
            o[nf][2] *= cB; o[nf][3] *= cB;
        }

        // ---- O += P @ V  (P fragments = packs of S fragments) ----
#pragma unroll
        for (int ksV = 0; ksV < 4; ksV++) {
            uint32_t pa[4];
            pa[0] = packh2(s[2 * ksV][0], s[2 * ksV][1]);
            pa[1] = packh2(s[2 * ksV][2], s[2 * ksV][3]);
            pa[2] = packh2(s[2 * ksV + 1][0], s[2 * ksV + 1][1]);
            pa[3] = packh2(s[2 * ksV + 1][2], s[2 * ksV + 1][3]);
#pragma unroll
            for (int nf = 0; nf < 8; nf++) {
                const int pl = lane ^ ((nf & 3) << 2);
                uint2 v = *(const uint2*)&Vs[(nf * 4 + ksV) * 64 + pl * 2];
                uint32_t bb[2] = {v.x, v.y};
                mma_f16(o[nf], pa, bb);
            }
        }

        // ---- store next tile into other buffer, then sync ----
        if (more) store_kv((ti & 1) ^ 1, kpre, vpre);
        __syncthreads();
    }

    // ---- epilogue: y = O / l -> g_y[b, t, h*64 + e] ----
    const float iA = 1.f / lA;
    const float iB = 1.f / lB;
    const int trA = i0 + w * 16 + (lane >> 2);
    const int ec = 2 * (lane & 3);
#pragma unroll
    for (int nf = 0; nf < 8; nf++) {
        const int e = nf * 8 + ec;
        float2 vA, vB;
        vA.x = o[nf][0] * iA; vA.y = o[nf][1] * iA;
        vB.x = o[nf][2] * iB; vB.y = o[nf][3] * iB;
        *(float2*)&g_y[((size_t)b * cfg::T + trA) * cfg::C + h * 64 + e] = vA;
        *(float2*)&g_y[((size_t)b * cfg::T + trA + 8) * cfg::C + h * 64 + e] = vB;
    }
}

// ---------------------------------------------------------------------------
extern "C" void kernel_launch(void* const* d_in, const int* in_sizes, int n_in,
                              void* d_out, int out_size) {
    const float* x     = (const float*)d_in[0];
    const float* kcch  = (const float*)d_in[1];
    const float* vcch  = (const float*)d_in[2];
    const float* Wqkv  = (const float*)d_in[3];
    const float* bqkv  = (const float*)d_in[4];
    const float* Wproj = (const float*)d_in[5];
    const float* bproj = (const float*)d_in[6];
    float* out = (float*)d_out;

    // 1) QKV projection + head split (fp16 mma)
    gemm_mma<cfg::NQKV, 0><<<dim3(cfg::NQKV / 128, cfg::M / 128), 256,
                             GM_SMEM_BYTES>>>(x, Wqkv, bqkv, nullptr);

    // 2) Flash attention (fp16 mma, double-buffered K/V)
    attn_mma<<<dim3(cfg::T / 128, cfg::H, cfg::B), 256, AT_SMEM_BYTES>>>(kcch, vcch);

    // 3) Output projection (fp16 mma)
    gemm_mma<cfg::C, 1><<<dim3(cfg::C / 128, cfg::M / 128), 256,
                          GM_SMEM_BYTES>>>(nullptr, Wproj, bproj, out);
}

// round 11
// speedup vs baseline: 6.1329x; 1.1422x over previous
#include <cuda_runtime.h>
#include <cuda_fp16.h>
#include <math_constants.h>
#include <cstdint>
#include <cstddef>

// Problem constants
namespace cfg {
constexpr int B = 8, T = 512, C = 1024, H = 16, E = 64, L = 2048;
constexpr int M = B * T;        // 4096 rows for both GEMMs
constexpr int NQKV = 3 * C;     // 3072
constexpr int NCT = L / 64;     // 32 cache key-tiles
}

// Scratch (device globals — no allocation allowed)
__device__ float g_q[cfg::B * cfg::H * cfg::T * cfg::E];   // (B,H,T,E) fp32
__device__ float g_k[cfg::B * cfg::H * cfg::T * cfg::E];
__device__ float g_v[cfg::B * cfg::H * cfg::T * cfg::E];
__device__ __half g_xh[cfg::M * cfg::C];                   // x in fp16
__device__ __half g_wqkvh[cfg::C * cfg::NQKV];             // Wqkv fp16 [K][N]
__device__ __half g_wprojh[cfg::C * cfg::C];               // Wproj fp16 [K][N]
__device__ __half g_yh[cfg::M * cfg::C];                   // attention out fp16

// ---------------------------------------------------------------------------
// helpers
// ---------------------------------------------------------------------------
__device__ __forceinline__ uint32_t packh2(float lo, float hi) {
    __half2 h = __floats2half2_rn(lo, hi);
    return *(uint32_t*)&h;
}

__device__ __forceinline__ uint32_t smem_u32(const void* p) {
    uint32_t a;
    asm("{ .reg .u64 t; cvta.to.shared.u64 t, %1; cvt.u32.u64 %0, t; }"
        : "=r"(a) : "l"(p));
    return a;
}

// D(16x8,f32) += A(16x16,f16) * B(16x8,f16)
__device__ __forceinline__ void mma_f16(float* d, const uint32_t* a,
                                        const uint32_t* b) {
    asm volatile(
        "mma.sync.aligned.m16n8k16.row.col.f32.f16.f16.f32 "
        "{%0,%1,%2,%3}, {%4,%5,%6,%7}, {%8,%9}, {%0,%1,%2,%3};"
        : "+f"(d[0]), "+f"(d[1]), "+f"(d[2]), "+f"(d[3])
        : "r"(a[0]), "r"(a[1]), "r"(a[2]), "r"(a[3]), "r"(b[0]), "r"(b[1]));
}

#define CP16(dst, gsrc) \
    asm volatile("cp.async.cg.shared.global [%0], [%1], 16;" \
                 :: "r"(dst), "l"(gsrc) : "memory")
#define CP_COMMIT() asm volatile("cp.async.commit_group;" ::: "memory")
#define CP_WAIT2()  asm volatile("cp.async.wait_group 2;" ::: "memory")

#define LDSM_X4(r0, r1, r2, r3, addr) \
    asm volatile("ldmatrix.sync.aligned.m8n8.x4.shared.b16 {%0,%1,%2,%3}, [%4];" \
                 : "=r"(r0), "=r"(r1), "=r"(r2), "=r"(r3) : "r"(addr))
#define LDSM_X4_T(r0, r1, r2, r3, addr) \
    asm volatile("ldmatrix.sync.aligned.m8n8.x4.trans.shared.b16 {%0,%1,%2,%3}, [%4];" \
                 : "=r"(r0), "=r"(r1), "=r"(r2), "=r"(r3) : "r"(addr))

// ---------------------------------------------------------------------------
// fp32 -> fp16 convert kernels (streaming; WHICH selects fixed destination)
// ---------------------------------------------------------------------------
template <int WHICH>
__global__ __launch_bounds__(256) void cvt16(const float* __restrict__ src) {
    __half* dst = (WHICH == 0) ? g_xh : (WHICH == 1) ? g_wqkvh : g_wprojh;
    const int i = blockIdx.x * 256 + threadIdx.x;
    const float4 v = ((const float4*)src)[i];
    uint32_t* d = (uint32_t*)dst;
    d[2 * i + 0] = packh2(v.x, v.y);
    d[2 * i + 1] = packh2(v.z, v.w);
}

// ---------------------------------------------------------------------------
// fp16 GEMM, cp.async 4-stage + ldmatrix. 128x128 CTA tile, BK=32, 8 warps
// (2m x 4n), warp tile 64x32 = 4x4 frags m16n8k16.
// MODE 0: out = x @ Wqkv + b -> scatter fp32 to g_q/g_k/g_v (B,H,T,E)
// MODE 1: out = y @ Wproj + b -> dense fp32 `out`
//
// SMEM per stage (bytes): A 128 rows x 80B (32 halves + pad) = 10240;
//                         B 32 k-rows x 256B (128 halves, j^=(k&7)) = 8192.
// Stage stride 18432; 4 stages; bias[128]f at 73728. Total 74240 B.
// ---------------------------------------------------------------------------
constexpr int GS_STAGE = 18432;
constexpr int GS_BOFF = 10240;
constexpr int GS_SMEM_BYTES = 4 * GS_STAGE + 512;   // 74240

template <int N, int MODE>
__global__ __launch_bounds__(256, 2) void gemm_cp(const float* __restrict__ bias,
                                                  float* __restrict__ out) {
    extern __shared__ uint32_t sh[];
    float* biasS = (float*)((char*)sh + 4 * GS_STAGE);

    const int t = threadIdx.x;
    const int lane = t & 31;
    const int wid = t >> 5;
    const int wm = wid >> 2;
    const int wn = wid & 3;
    const int m0 = blockIdx.y * 128;
    const int n0 = blockIdx.x * 128;

    const __half* Ab = (MODE == 1) ? g_yh : g_xh;
    const __half* Wh = (MODE == 1) ? g_wprojh : g_wqkvh;
    if (t < 128) biasS[t] = bias[n0 + t];

    const uint32_t sbase = smem_u32(sh);

    // ---- cp.async loader mapping ----
    // A: thread -> row (t>>1), 16B chunks c4 = (t&1)*2, +1
    const uint32_t asd = sbase + (t >> 1) * 80 + (t & 1) * 32;
    const __half* agp = Ab + (size_t)(m0 + (t >> 1)) * cfg::C + (t & 1) * 16;
    // B: thread -> k-row (t>>3), 16B chunks j0 = (t&7)*2, +1 (swizzled)
    const int bk = t >> 3;
    const int bj0 = (t & 7) * 2;
    const uint32_t bsd0 = sbase + GS_BOFF + bk * 256 + ((bj0) ^ (bk & 7)) * 16;
    const uint32_t bsd1 = sbase + GS_BOFF + bk * 256 + ((bj0 + 1) ^ (bk & 7)) * 16;
    const __half* bgp = Wh + (size_t)bk * N + n0 + bj0 * 8;

    uint64_t agg, bgg;
    asm("cvta.to.global.u64 %0, %1;" : "=l"(agg) : "l"(agp));
    asm("cvta.to.global.u64 %0, %1;" : "=l"(bgg) : "l"(bgp));

    auto load_stage = [&](int stage, int ck) {
        const uint32_t so = stage * GS_STAGE;
        const uint64_t ga = agg + (uint64_t)ck * 64;          // 32 halves
        CP16(asd + so, ga);
        CP16(asd + so + 16, ga + 16);
        const uint64_t gb = bgg + (uint64_t)ck * 32 * N * 2;  // 32 k-rows
        CP16(bsd0 + so, gb);
        CP16(bsd1 + so, gb + 16);
    };

    // ---- ldmatrix frag address precompute ----
    const int l7 = lane & 7;
    const int lm = (lane >> 3) & 1;
    const int lh = lane >> 4;
    const uint32_t aoff = sbase + (wm * 64 + l7 + 8 * lm) * 80 + lh * 16;
    const uint32_t boff = sbase + GS_BOFF + (l7 + 8 * lm) * 256;
    const uint32_t jx0 = (uint32_t)(((wn * 4 + 0 + lh) ^ l7) * 16);
    const uint32_t jx1 = (uint32_t)(((wn * 4 + 2 + lh) ^ l7) * 16);

    float acc[4][4][4];
#pragma unroll
    for (int im = 0; im < 4; im++)
#pragma unroll
        for (int in = 0; in < 4; in++)
#pragma unroll
            for (int k = 0; k < 4; k++) acc[im][in][k] = 0.f;

    auto compute = [&](int stage) {
        const uint32_t so = stage * GS_STAGE;
#pragma unroll
        for (int ks = 0; ks < 2; ks++) {
            uint32_t a[4][4];
#pragma unroll
            for (int mf = 0; mf < 4; mf++)
                LDSM_X4(a[mf][0], a[mf][1], a[mf][2], a[mf][3],
                        aoff + so + mf * 1280 + ks * 32);
            uint32_t bb[4][2];
            {
                uint32_t r0, r1, r2, r3;
                LDSM_X4_T(r0, r1, r2, r3, boff + so + ks * 4096 + jx0);
                bb[0][0] = r0; bb[0][1] = r1; bb[1][0] = r2; bb[1][1] = r3;
                LDSM_X4_T(r0, r1, r2, r3, boff + so + ks * 4096 + jx1);
                bb[2][0] = r0; bb[2][1] = r1; bb[3][0] = r2; bb[3][1] = r3;
            }
#pragma unroll
            for (int mf = 0; mf < 4; mf++)
#pragma unroll
                for (int in = 0; in < 4; in++)
                    mma_f16(acc[mf][in], a[mf], bb[in]);
        }
    };

    // ---- 4-stage pipeline ----
    load_stage(0, 0); CP_COMMIT();
    load_stage(1, 1); CP_COMMIT();
    load_stage(2, 2); CP_COMMIT();

    for (int ck = 0; ck < 32; ck++) {
        CP_WAIT2();
        __syncthreads();
        compute(ck & 3);
        if (ck + 3 < 32) load_stage((ck + 3) & 3, ck + 3);
        CP_COMMIT();
    }

    // ---- epilogue ----
    const int rbase = lane >> 2;
    const int cpair = (lane & 3) * 2;

    if (MODE == 0) {
        const int sel = n0 >> 10;
        float* dstbuf = (sel == 0) ? g_q : (sel == 1) ? g_k : g_v;
#pragma unroll
        for (int im = 0; im < 4; im++) {
            const int mrow = m0 + (wm * 4 + im) * 16 + rbase;
#pragma unroll
            for (int in = 0; in < 4; in++) {
                const int nloc = (wn * 4 + in) * 8 + cpair;
                const int lc = (n0 & 1023) + nloc;
                const int h = lc >> 6;
                const int e = lc & 63;
                const float bx = biasS[nloc], by = biasS[nloc + 1];
#pragma unroll
                for (int rr = 0; rr < 2; rr++) {
                    const int m = mrow + rr * 8;
                    const int b = m >> 9;
                    const int tt = m & 511;
                    float2 v;
                    v.x = acc[im][in][rr * 2 + 0] + bx;
                    v.y = acc[im][in][rr * 2 + 1] + by;
                    *(float2*)&dstbuf[(((size_t)(b * cfg::H + h) * cfg::T) + tt) *
                                          cfg::E + e] = v;
                }
            }
        }
    } else {
#pragma unroll
        for (int im = 0; im < 4; im++) {
            const int mrow = m0 + (wm * 4 + im) * 16 + rbase;
#pragma unroll
            for (int in = 0; in < 4; in++) {
                const int nloc = (wn * 4 + in) * 8 + cpair;
                const float bx = biasS[nloc], by = biasS[nloc + 1];
#pragma unroll
                for (int rr = 0; rr < 2; rr++) {
                    const int m = mrow + rr * 8;
                    float2 v;
                    v.x = acc[im][in][rr * 2 + 0] + bx;
                    v.y = acc[im][in][rr * 2 + 1] + by;
                    *(float2*)&out[(size_t)m * cfg::C + n0 + nloc] = v;
                }
            }
        }
    }
}

// ---------------------------------------------------------------------------
// Flash attention, fp16 m16n8k16 (R8 structure, validated). Only change:
// epilogue writes g_yh (fp16) for the cp.async proj GEMM.
// ---------------------------------------------------------------------------
constexpr int AT_SMEM_BYTES = 8192 * 4;   // 32768

__global__ __launch_bounds__(256, 2) void attn_mma(const float* __restrict__ kc,
                                                   const float* __restrict__ vc) {
    extern __shared__ uint32_t sh[];
    const int t = threadIdx.x;
    const int lane = t & 31;
    const int w = t >> 5;
    const int qt = blockIdx.x;
    const int h = blockIdx.y;
    const int b = blockIdx.z;
    const int i0 = qt * 128;

    const size_t bh = (size_t)b * cfg::H + h;
    const float* qb = g_q + (bh * cfg::T + i0) * 64;
    const float* kcb = kc + bh * cfg::L * 64;
    const float* vcb = vc + bh * cfg::L * 64;
    const float* knb = g_k + bh * cfg::T * 64;
    const float* vnb = g_v + bh * cfg::T * 64;

    // ---- Q fragments in registers, scale folded ----
    uint32_t qf[4][4];
    {
        const float scale = 0.125f;  // 1/sqrt(64)
        const int r = w * 16 + (lane >> 2);
        const int c2 = 2 * (lane & 3);
        const float* q0 = qb + (size_t)r * 64 + c2;
        const float* q8 = qb + (size_t)(r + 8) * 64 + c2;
#pragma unroll
        for (int ks = 0; ks < 4; ks++) {
            float2 x0 = *(const float2*)(q0 + 16 * ks);
            float2 x1 = *(const float2*)(q8 + 16 * ks);
            float2 x2 = *(const float2*)(q0 + 16 * ks + 8);
            float2 x3 = *(const float2*)(q8 + 16 * ks + 8);
            qf[ks][0] = packh2(x0.x * scale, x0.y * scale);
            qf[ks][1] = packh2(x1.x * scale, x1.y * scale);
            qf[ks][2] = packh2(x2.x * scale, x2.y * scale);
            qf[ks][3] = packh2(x3.x * scale, x3.y * scale);
        }
    }

    // ---- K loader mapping ----
    const int key = t >> 2;
    const int keoff = key * 64 + 4 * (t & 3);
    const uint32_t kbase =
        (uint32_t)((key >> 3) * 256 +
                   ((((key & 7) << 2) | (2 * (t & 1))) * 2) + ((t & 2) ? 1 : 0));
    // ---- V loader mapping ----
    const int kp = t >> 3;
    const int vm = (t >> 1) & 3;
    const uint32_t vbase =
        (uint32_t)((((t & 7) >> 1) * 4 + (kp >> 3)) * 64 +
                   ((4 * (t & 1)) << 3) + (kp & 3) * 2 + ((kp & 4) ? 1 : 0));
    const int voff = 2 * kp * 64 + 4 * (t & 7);

    float o[8][4];
#pragma unroll
    for (int nf = 0; nf < 8; nf++)
#pragma unroll
        for (int r = 0; r < 4; r++) o[nf][r] = 0.f;
    float mA = -CUDART_INF_F, mB = -CUDART_INF_F, lA = 0.f, lB = 0.f;

    const int ntiles = 34 + 2 * qt;

    auto tile_ptrs = [&](int ti, const float*& ks_, const float*& vs_) {
        if (ti < cfg::NCT) {
            ks_ = kcb + (size_t)ti * 4096;
            vs_ = vcb + (size_t)ti * 4096;
        } else {
            ks_ = knb + (size_t)(ti - cfg::NCT) * 4096;
            vs_ = vnb + (size_t)(ti - cfg::NCT) * 4096;
        }
    };
    auto load_kv = [&](const float* ks_, const float* vs_, float4* kpre,
                       float4* vpre) {
#pragma unroll
        for (int k4 = 0; k4 < 4; k4++)
            kpre[k4] = *(const float4*)(ks_ + keoff + 16 * k4);
#pragma unroll
        for (int i2 = 0; i2 < 2; i2++) {
            vpre[2 * i2] = *(const float4*)(vs_ + voff + 32 * i2);
            vpre[2 * i2 + 1] = *(const float4*)(vs_ + voff + 32 * i2 + 64);
        }
    };
    auto store_kv = [&](int buf, const float4* kpre, const float4* vpre) {
        uint32_t* kd = sh + buf * 4096;
        uint32_t* vd = sh + buf * 4096 + 2048;
#pragma unroll
        for (int k4 = 0; k4 < 4; k4++) {
            const float* vv = (const float*)&kpre[k4];
#pragma unroll
            for (int hh = 0; hh < 2; hh++)
                kd[kbase + k4 * 64 + hh * 2] = packh2(vv[2 * hh], vv[2 * hh + 1]);
        }
#pragma unroll
        for (int i2 = 0; i2 < 2; i2++) {
            const float* lo = (const float*)&vpre[2 * i2];
            const float* hi = (const float*)&vpre[2 * i2 + 1];
#pragma unroll
            for (int j = 0; j < 4; j++)
                vd[vbase + i2 * 1024 + ((j ^ vm) << 3)] = packh2(lo[j], hi[j]);
        }
    };

    {
        const float *ks_, *vs_;
        tile_ptrs(0, ks_, vs_);
        float4 kpre[4], vpre[4];
        load_kv(ks_, vs_, kpre, vpre);
        store_kv(0, kpre, vpre);
    }
    __syncthreads();

    for (int ti = 0; ti < ntiles; ti++) {
        const int cur = (ti & 1) * 4096;
        const uint32_t* Ks = sh + cur;
        const uint32_t* Vs = sh + cur + 2048;

        float4 kpre[4], vpre[4];
        const bool more = (ti + 1 < ntiles);
        if (more) {
            const float *ks_, *vs_;
            tile_ptrs(ti + 1, ks_, vs_);
            load_kv(ks_, vs_, kpre, vpre);
        }

        // ---- S = Q @ K^T ----
        float s[8][4];
#pragma unroll
        for (int nf = 0; nf < 8; nf++)
#pragma unroll
            for (int r = 0; r < 4; r++) s[nf][r] = 0.f;
#pragma unroll
        for (int ks = 0; ks < 4; ks++) {
#pragma unroll
            for (int nf = 0; nf < 8; nf++) {
                uint2 v = *(const uint2*)&Ks[(nf * 4 + ks) * 64 + lane * 2];
                uint32_t bb[2] = {v.x, v.y};
                mma_f16(s[nf], qf[ks], bb);
            }
        }

        // ---- online softmax ----
        const bool diag = (ti >= cfg::NCT + 2 * qt);
        const int rowA = i0 + w * 16 + (lane >> 2);
        const int colb = (ti - cfg::NCT) * 64 + 2 * (lane & 3);
        float mxA = -CUDART_INF_F, mxB = -CUDART_INF_F;
#pragma unroll
        for (int nf = 0; nf < 8; nf++) {
            if (diag) {
                const int c0 = colb + nf * 8;
                if (c0 > rowA) s[nf][0] = -CUDART_INF_F;
                if (c0 + 1 > rowA) s[nf][1] = -CUDART_INF_F;
                if (c0 > rowA + 8) s[nf][2] = -CUDART_INF_F;
                if (c0 + 1 > rowA + 8) s[nf][3] = -CUDART_INF_F;
            }
            mxA = fmaxf(mxA, fmaxf(s[nf][0], s[nf][1]));
            mxB = fmaxf(mxB, fmaxf(s[nf][2], s[nf][3]));
        }
        mxA = fmaxf(mxA, __shfl_xor_sync(0xffffffffu, mxA, 1));
        mxA = fmaxf(mxA, __shfl_xor_sync(0xffffffffu, mxA, 2));
        mxB = fmaxf(mxB, __shfl_xor_sync(0xffffffffu, mxB, 1));
        mxB = fmaxf(mxB, __shfl_xor_sync(0xffffffffu, mxB, 2));

        const float mAn = fmaxf(mA, mxA);
        const float mBn = fmaxf(mB, mxB);
        const float cA = __expf(mA - mAn);
        const float cB = __expf(mB - mBn);
        mA = mAn; mB = mBn;

        float sA = 0.f, sB = 0.f;
#pragma unroll
        for (int nf = 0; nf < 8; nf++) {
            s[nf][0] = __expf(s[nf][0] - mA); sA += s[nf][0];
            s[nf][1] = __expf(s[nf][1] - mA); sA += s[nf][1];
            s[nf][2] = __expf(s[nf][2] - mB); sB += s[nf][2];
            s[nf][3] = __expf(s[nf][3] - mB); sB += s[nf][3];
        }
        sA += __shfl_xor_sync(0xffffffffu, sA, 1);
        sA += __shfl_xor_sync(0xffffffffu, sA, 2);
        sB += __shfl_xor_sync(0xffffffffu, sB, 1);
        sB += __shfl_xor_sync(0xffffffffu, sB, 2);
        lA = lA * cA + sA;
        lB = lB * cB + sB;
#pragma unroll
        for (int nf = 0; nf < 8; nf++) {
            o[nf][0] *= cA; o[nf][1] *= cA;
            o[nf][2] *= cB; o[nf][3] *= cB;
        }

        // ---- O += P @ V ----
#pragma unroll
        for (int ksV = 0; ksV < 4; ksV++) {
            uint32_t pa[4];
            pa[0] = packh2(s[2 * ksV][0], s[2 * ksV][1]);
            pa[1] = packh2(s[2 * ksV][2], s[2 * ksV][3]);
            pa[2] = packh2(s[2 * ksV + 1][0], s[2 * ksV + 1][1]);
            pa[3] = packh2(s[2 * ksV + 1][2], s[2 * ksV + 1][3]);
#pragma unroll
            for (int nf = 0; nf < 8; nf++) {
                const int pl = lane ^ ((nf & 3) << 2);
                uint2 v = *(const uint2*)&Vs[(nf * 4 + ksV) * 64 + pl * 2];
                uint32_t bb[2] = {v.x, v.y};
                mma_f16(o[nf], pa, bb);
            }
        }

        if (more) store_kv((ti & 1) ^ 1, kpre, vpre);
        __syncthreads();
    }

    // ---- epilogue: y = O / l -> g_yh (fp16) ----
    const float iA = 1.f / lA;
    const float iB = 1.f / lB;
    const int trA = i0 + w * 16 + (lane >> 2);
    const int ec = 2 * (lane & 3);
    uint32_t* yh = (uint32_t*)g_yh;
#pragma unroll
    for (int nf = 0; nf < 8; nf++) {
        const int e = nf * 8 + ec;
        const size_t iA2 = (((size_t)b * cfg::T + trA) * cfg::C + h * 64 + e) >> 1;
        const size_t iB2 = (((size_t)b * cfg::T + trA + 8) * cfg::C + h * 64 + e) >> 1;
        yh[iA2] = packh2(o[nf][0] * iA, o[nf][1] * iA);
        yh[iB2] = packh2(o[nf][2] * iB, o[nf][3] * iB);
    }
}

// ---------------------------------------------------------------------------
extern "C" void kernel_launch(void* const* d_in, const int* in_sizes, int n_in,
                              void* d_out, int out_size) {
    const float* x     = (const float*)d_in[0];
    const float* kcch  = (const float*)d_in[1];
    const float* vcch  = (const float*)d_in[2];
    const float* Wqkv  = (const float*)d_in[3];
    const float* bqkv  = (const float*)d_in[4];
    const float* Wproj = (const float*)d_in[5];
    const float* bproj = (const float*)d_in[6];
    float* out = (float*)d_out;

    cudaFuncSetAttribute(gemm_cp<cfg::NQKV, 0>,
                         cudaFuncAttributeMaxDynamicSharedMemorySize, GS_SMEM_BYTES);
    cudaFuncSetAttribute(gemm_cp<cfg::C, 1>,
                         cudaFuncAttributeMaxDynamicSharedMemorySize, GS_SMEM_BYTES);

    // 0) fp32 -> fp16 operand conversion
    cvt16<0><<<cfg::M * cfg::C / 1024, 256>>>(x);
    cvt16<1><<<cfg::C * cfg::NQKV / 1024, 256>>>(Wqkv);
    cvt16<2><<<cfg::C * cfg::C / 1024, 256>>>(Wproj);

    // 1) QKV projection + head split (cp.async + ldmatrix fp16)
    gemm_cp<cfg::NQKV, 0><<<dim3(cfg::NQKV / 128, cfg::M / 128), 256,
                            GS_SMEM_BYTES>>>(bqkv, nullptr);

    // 2) Flash attention (fp16 mma)
    attn_mma<<<dim3(cfg::T / 128, cfg::H, cfg::B), 256, AT_SMEM_BYTES>>>(kcch, vcch);

    // 3) Output projection (cp.async + ldmatrix fp16)
    gemm_cp<cfg::C, 1><<<dim3(cfg::C / 128, cfg::M / 128), 256,
                         GS_SMEM_BYTES>>>(bproj, out);
}

// round 12
// speedup vs baseline: 7.0922x; 1.1564x over previous
#include <cuda_runtime.h>
#include <cuda_fp16.h>
#include <math_constants.h>
#include <cstdint>
#include <cstddef>

// Problem constants
namespace cfg {
constexpr int B = 8, T = 512, C = 1024, H = 16, E = 64, L = 2048;
constexpr int M = B * T;        // 4096 rows for both GEMMs
constexpr int NQKV = 3 * C;     // 3072
constexpr int NCT = L / 64;     // 32 cache key-tiles
}

// Scratch (device globals — no allocation allowed); all operands fp16
__device__ __half g_xh[cfg::M * cfg::C];                   // x
__device__ __half g_wqkvh[cfg::C * cfg::NQKV];             // Wqkv [K][N]
__device__ __half g_wprojh[cfg::C * cfg::C];               // Wproj [K][N]
__device__ __half g_qh[cfg::B * cfg::H * cfg::T * cfg::E]; // q (B,H,T,E)
__device__ __half g_kh[cfg::B * cfg::H * cfg::T * cfg::E]; // new k
__device__ __half g_vh[cfg::B * cfg::H * cfg::T * cfg::E]; // new v
__device__ __half g_kch[cfg::B * cfg::H * cfg::L * cfg::E];// k cache fp16
__device__ __half g_vch[cfg::B * cfg::H * cfg::L * cfg::E];// v cache fp16
__device__ __half g_yh[cfg::M * cfg::C];                   // attention out

// ---------------------------------------------------------------------------
// helpers
// ---------------------------------------------------------------------------
__device__ __forceinline__ uint32_t packh2(float lo, float hi) {
    __half2 h = __floats2half2_rn(lo, hi);
    return *(uint32_t*)&h;
}

__device__ __forceinline__ uint32_t hmul2u(uint32_t x, __half2 s) {
    __half2 v = *(__half2*)&x;
    v = __hmul2(v, s);
    return *(uint32_t*)&v;
}

__device__ __forceinline__ float ex2(float x) {
    float y;
    asm("ex2.approx.ftz.f32 %0, %1;" : "=f"(y) : "f"(x));
    return y;
}

__device__ __forceinline__ uint32_t smem_u32(const void* p) {
    uint32_t a;
    asm("{ .reg .u64 t; cvta.to.shared.u64 t, %1; cvt.u32.u64 %0, t; }"
        : "=r"(a) : "l"(p));
    return a;
}

// D(16x8,f32) += A(16x16,f16) * B(16x8,f16)
__device__ __forceinline__ void mma_f16(float* d, const uint32_t* a,
                                        const uint32_t* b) {
    asm volatile(
        "mma.sync.aligned.m16n8k16.row.col.f32.f16.f16.f32 "
        "{%0,%1,%2,%3}, {%4,%5,%6,%7}, {%8,%9}, {%0,%1,%2,%3};"
        : "+f"(d[0]), "+f"(d[1]), "+f"(d[2]), "+f"(d[3])
        : "r"(a[0]), "r"(a[1]), "r"(a[2]), "r"(a[3]), "r"(b[0]), "r"(b[1]));
}

#define CP16(dst, gsrc) \
    asm volatile("cp.async.cg.shared.global [%0], [%1], 16;" \
                 :: "r"(dst), "l"(gsrc) : "memory")
#define CP_COMMIT() asm volatile("cp.async.commit_group;" ::: "memory")
#define CP_WAIT2()  asm volatile("cp.async.wait_group 2;" ::: "memory")
#define CP_WAIT1()  asm volatile("cp.async.wait_group 1;" ::: "memory")

#define LDSM_X4(r0, r1, r2, r3, addr) \
    asm volatile("ldmatrix.sync.aligned.m8n8.x4.shared.b16 {%0,%1,%2,%3}, [%4];" \
                 : "=r"(r0), "=r"(r1), "=r"(r2), "=r"(r3) : "r"(addr))
#define LDSM_X4_T(r0, r1, r2, r3, addr) \
    asm volatile("ldmatrix.sync.aligned.m8n8.x4.trans.shared.b16 {%0,%1,%2,%3}, [%4];" \
                 : "=r"(r0), "=r"(r1), "=r"(r2), "=r"(r3) : "r"(addr))

// ---------------------------------------------------------------------------
// fp32 -> fp16 convert kernels (streaming)
// ---------------------------------------------------------------------------
template <int WHICH>
__global__ __launch_bounds__(256) void cvt16(const float* __restrict__ src) {
    __half* dst = (WHICH == 0) ? g_xh
                : (WHICH == 1) ? g_wqkvh
                : (WHICH == 2) ? g_wprojh
                : (WHICH == 3) ? g_kch : g_vch;
    const int i = blockIdx.x * 256 + threadIdx.x;
    const float4 v = ((const float4*)src)[i];
    uint32_t* d = (uint32_t*)dst;
    d[2 * i + 0] = packh2(v.x, v.y);
    d[2 * i + 1] = packh2(v.z, v.w);
}

// ---------------------------------------------------------------------------
// fp16 GEMM, cp.async 4-stage + ldmatrix (validated R11). 128x128 tile, BK=32.
// MODE 0: out = x @ Wqkv + b -> scatter fp16 to g_qh/g_kh/g_vh (B,H,T,E)
// MODE 1: out = y @ Wproj + b -> dense fp32 `out`
// ---------------------------------------------------------------------------
constexpr int GS_STAGE = 18432;
constexpr int GS_BOFF = 10240;
constexpr int GS_SMEM_BYTES = 4 * GS_STAGE + 512;   // 74240

template <int N, int MODE>
__global__ __launch_bounds__(256, 2) void gemm_cp(const float* __restrict__ bias,
                                                  float* __restrict__ out) {
    extern __shared__ uint32_t sh[];
    float* biasS = (float*)((char*)sh + 4 * GS_STAGE);

    const int t = threadIdx.x;
    const int lane = t & 31;
    const int wid = t >> 5;
    const int wm = wid >> 2;
    const int wn = wid & 3;
    const int m0 = blockIdx.y * 128;
    const int n0 = blockIdx.x * 128;

    const __half* Ab = (MODE == 1) ? g_yh : g_xh;
    const __half* Wh = (MODE == 1) ? g_wprojh : g_wqkvh;
    if (t < 128) biasS[t] = bias[n0 + t];

    const uint32_t sbase = smem_u32(sh);

    const uint32_t asd = sbase + (t >> 1) * 80 + (t & 1) * 32;
    const __half* agp = Ab + (size_t)(m0 + (t >> 1)) * cfg::C + (t & 1) * 16;
    const int bk = t >> 3;
    const int bj0 = (t & 7) * 2;
    const uint32_t bsd0 = sbase + GS_BOFF + bk * 256 + ((bj0) ^ (bk & 7)) * 16;
    const uint32_t bsd1 = sbase + GS_BOFF + bk * 256 + ((bj0 + 1) ^ (bk & 7)) * 16;
    const __half* bgp = Wh + (size_t)bk * N + n0 + bj0 * 8;

    uint64_t agg, bgg;
    asm("cvta.to.global.u64 %0, %1;" : "=l"(agg) : "l"(agp));
    asm("cvta.to.global.u64 %0, %1;" : "=l"(bgg) : "l"(bgp));

    auto load_stage = [&](int stage, int ck) {
        const uint32_t so = stage * GS_STAGE;
        const uint64_t ga = agg + (uint64_t)ck * 64;
        CP16(asd + so, ga);
        CP16(asd + so + 16, ga + 16);
        const uint64_t gb = bgg + (uint64_t)ck * 32 * N * 2;
        CP16(bsd0 + so, gb);
        CP16(bsd1 + so, gb + 16);
    };

    const int l7 = lane & 7;
    const int lm = (lane >> 3) & 1;
    const int lh = lane >> 4;
    const uint32_t aoff = sbase + (wm * 64 + l7 + 8 * lm) * 80 + lh * 16;
    const uint32_t boff = sbase + GS_BOFF + (l7 + 8 * lm) * 256;
    const uint32_t jx0 = (uint32_t)(((wn * 4 + 0 + lh) ^ l7) * 16);
    const uint32_t jx1 = (uint32_t)(((wn * 4 + 2 + lh) ^ l7) * 16);

    float acc[4][4][4];
#pragma unroll
    for (int im = 0; im < 4; im++)
#pragma unroll
        for (int in = 0; in < 4; in++)
#pragma unroll
            for (int k = 0; k < 4; k++) acc[im][in][k] = 0.f;

    auto compute = [&](int stage) {
        const uint32_t so = stage * GS_STAGE;
#pragma unroll
        for (int ks = 0; ks < 2; ks++) {
            uint32_t a[4][4];
#pragma unroll
            for (int mf = 0; mf < 4; mf++)
                LDSM_X4(a[mf][0], a[mf][1], a[mf][2], a[mf][3],
                        aoff + so + mf * 1280 + ks * 32);
            uint32_t bb[4][2];
            {
                uint32_t r0, r1, r2, r3;
                LDSM_X4_T(r0, r1, r2, r3, boff + so + ks * 4096 + jx0);
                bb[0][0] = r0; bb[0][1] = r1; bb[1][0] = r2; bb[1][1] = r3;
                LDSM_X4_T(r0, r1, r2, r3, boff + so + ks * 4096 + jx1);
                bb[2][0] = r0; bb[2][1] = r1; bb[3][0] = r2; bb[3][1] = r3;
            }
#pragma unroll
            for (int mf = 0; mf < 4; mf++)
#pragma unroll
                for (int in = 0; in < 4; in++)
                    mma_f16(acc[mf][in], a[mf], bb[in]);
        }
    };

    load_stage(0, 0); CP_COMMIT();
    load_stage(1, 1); CP_COMMIT();
    load_stage(2, 2); CP_COMMIT();

    for (int ck = 0; ck < 32; ck++) {
        CP_WAIT2();
        __syncthreads();
        compute(ck & 3);
        if (ck + 3 < 32) load_stage((ck + 3) & 3, ck + 3);
        CP_COMMIT();
    }

    const int rbase = lane >> 2;
    const int cpair = (lane & 3) * 2;

    if (MODE == 0) {
        const int sel = n0 >> 10;
        __half* dstbuf = (sel == 0) ? g_qh : (sel == 1) ? g_kh : g_vh;
#pragma unroll
        for (int im = 0; im < 4; im++) {
            const int mrow = m0 + (wm * 4 + im) * 16 + rbase;
#pragma unroll
            for (int in = 0; in < 4; in++) {
                const int nloc = (wn * 4 + in) * 8 + cpair;
                const int lc = (n0 & 1023) + nloc;
                const int h = lc >> 6;
                const int e = lc & 63;
                const float bx = biasS[nloc], by = biasS[nloc + 1];
#pragma unroll
                for (int rr = 0; rr < 2; rr++) {
                    const int m = mrow + rr * 8;
                    const int b = m >> 9;
                    const int tt = m & 511;
                    *(uint32_t*)&dstbuf[(((size_t)(b * cfg::H + h) * cfg::T) + tt) *
                                            cfg::E + e] =
                        packh2(acc[im][in][rr * 2 + 0] + bx,
                               acc[im][in][rr * 2 + 1] + by);
                }
            }
        }
    } else {
#pragma unroll
        for (int im = 0; im < 4; im++) {
            const int mrow = m0 + (wm * 4 + im) * 16 + rbase;
#pragma unroll
            for (int in = 0; in < 4; in++) {
                const int nloc = (wn * 4 + in) * 8 + cpair;
                const float bx = biasS[nloc], by = biasS[nloc + 1];
#pragma unroll
                for (int rr = 0; rr < 2; rr++) {
                    const int m = mrow + rr * 8;
                    float2 v;
                    v.x = acc[im][in][rr * 2 + 0] + bx;
                    v.y = acc[im][in][rr * 2 + 1] + by;
                    *(float2*)&out[(size_t)m * cfg::C + n0 + nloc] = v;
                }
            }
        }
    }
}

// ---------------------------------------------------------------------------
// Flash attention, fp16 mma + cp.async (3-stage) + ldmatrix.
// CTA = (q-tile 128, head, batch); 8 warps; warp w owns rows w*16..+15.
// Q frags in registers (scale*log2e folded); softmax in exp2 domain.
// SMEM per stage: K 64x64 fp16 (8192 B) + V same (8192 B); 3 stages = 48 KB.
// Layout: chunk(key r, e-chunk ec) at r*128 + ((ec ^ (r&7))<<4).
// K frags: non-trans ldmatrix (B = [n=key][k=e]); V frags: trans ([k=key][n=e]).
// ---------------------------------------------------------------------------
constexpr int AT_STAGE = 16384;
constexpr int AT_SMEM_BYTES = 3 * AT_STAGE;   // 49152

__global__ __launch_bounds__(256, 2) void attn_mma() {
    extern __shared__ uint32_t sh[];
    const uint32_t sbase = smem_u32(sh);
    const int t = threadIdx.x;
    const int lane = t & 31;
    const int w = t >> 5;
    const int qt = blockIdx.x;
    const int h = blockIdx.y;
    const int b = blockIdx.z;
    const int i0 = qt * 128;

    const size_t bh = (size_t)b * cfg::H + h;

    // ---- Q fragments (fp16 direct), scale*log2e folded ----
    uint32_t qf[4][4];
    {
        const __half2 hs = __float2half2_rn(0.125f * 1.44269504f);
        const int r = w * 16 + (lane >> 2);
        const int lq = lane & 3;
        const uint32_t* q0 = (const uint32_t*)g_qh + (bh * cfg::T + i0 + r) * 32;
        const uint32_t* q8 = q0 + 8 * 32;
#pragma unroll
        for (int ks = 0; ks < 4; ks++) {
            qf[ks][0] = hmul2u(q0[8 * ks + lq], hs);
            qf[ks][1] = hmul2u(q8[8 * ks + lq], hs);
            qf[ks][2] = hmul2u(q0[8 * ks + 4 + lq], hs);
            qf[ks][3] = hmul2u(q8[8 * ks + 4 + lq], hs);
        }
    }

    // ---- cp.async loader: thread covers (key kr, e-chunks ec0, ec0+1) ----
    const int kr = t >> 2;
    const int ec0 = (t & 3) * 2;
    const uint32_t ksm0 = (uint32_t)(kr * 128 + ((ec0 ^ (kr & 7)) << 4));
    const uint32_t ksm1 = (uint32_t)(kr * 128 + (((ec0 + 1) ^ (kr & 7)) << 4));
    const uint64_t goff = (uint64_t)kr * 128 + (uint64_t)ec0 * 16;
    const uint64_t gkc = (uint64_t)__cvta_generic_to_global(g_kch) + bh * 262144 + goff;
    const uint64_t gvc = (uint64_t)__cvta_generic_to_global(g_vch) + bh * 262144 + goff;
    const uint64_t gkn = (uint64_t)__cvta_generic_to_global(g_kh) + bh * 65536 + goff;
    const uint64_t gvn = (uint64_t)__cvta_generic_to_global(g_vh) + bh * 65536 + goff;

    auto load_stage = [&](int st, int ti) {
        uint64_t gk, gv;
        if (ti < cfg::NCT) {
            gk = gkc + (uint64_t)ti * 8192;
            gv = gvc + (uint64_t)ti * 8192;
        } else {
            gk = gkn + (uint64_t)(ti - cfg::NCT) * 8192;
            gv = gvn + (uint64_t)(ti - cfg::NCT) * 8192;
        }
        const uint32_t sb = sbase + st * AT_STAGE;
        CP16(sb + ksm0, gk);
        CP16(sb + ksm1, gk + 16);
        CP16(sb + 8192 + ksm0, gv);
        CP16(sb + 8192 + ksm1, gv + 16);
    };

    // ---- ldmatrix per-lane address components ----
    const int l7 = lane & 7;
    const int lmid = (lane >> 3) & 1;
    const int lhi = lane >> 4;
    // K: key = nfp*16 + lhi*8 + l7, ec = 2ks + lmid
    const uint32_t kb0 = (uint32_t)((lhi * 8 + l7) * 128);
    // V: key = 16ksV + lmid*8 + l7, ec = 2nfp + lhi
    const uint32_t vb0 = (uint32_t)((lmid * 8 + l7) * 128);

    float o[8][4];
#pragma unroll
    for (int nf = 0; nf < 8; nf++)
#pragma unroll
        for (int r = 0; r < 4; r++) o[nf][r] = 0.f;
    float mA = -CUDART_INF_F, mB = -CUDART_INF_F, lA = 0.f, lB = 0.f;

    const int ntiles = 34 + 2 * qt;

    load_stage(0, 0); CP_COMMIT();
    load_stage(1, 1); CP_COMMIT();

    int st = 0;
    for (int ti = 0; ti < ntiles; ti++) {
        CP_WAIT1();
        __syncthreads();
        const uint32_t kst = sbase + st * AT_STAGE;
        const uint32_t vst = kst + 8192;

        // ---- S = Q @ K^T (log2-scaled) ----
        float s[8][4];
#pragma unroll
        for (int nf = 0; nf < 8; nf++)
#pragma unroll
            for (int r = 0; r < 4; r++) s[nf][r] = 0.f;
#pragma unroll
        for (int ks = 0; ks < 4; ks++) {
            const uint32_t ecx = (uint32_t)(((2 * ks + lmid) ^ l7) << 4);
#pragma unroll
            for (int nfp = 0; nfp < 4; nfp++) {
                uint32_t r0, r1, r2, r3;
                LDSM_X4(r0, r1, r2, r3, kst + kb0 + nfp * 2048 + ecx);
                uint32_t b0[2] = {r0, r1};
                uint32_t b1[2] = {r2, r3};
                mma_f16(s[2 * nfp], qf[ks], b0);
                mma_f16(s[2 * nfp + 1], qf[ks], b1);
            }
        }

        // ---- online softmax (exp2 domain) ----
        const bool diag = (ti >= cfg::NCT + 2 * qt);
        const int rowA = i0 + w * 16 + (lane >> 2);
        const int colb = (ti - cfg::NCT) * 64 + 2 * (lane & 3);
        float mxA = -CUDART_INF_F, mxB = -CUDART_INF_F;
#pragma unroll
        for (int nf = 0; nf < 8; nf++) {
            if (diag) {
                const int c0 = colb + nf * 8;
                if (c0 > rowA) s[nf][0] = -CUDART_INF_F;
                if (c0 + 1 > rowA) s[nf][1] = -CUDART_INF_F;
                if (c0 > rowA + 8) s[nf][2] = -CUDART_INF_F;
                if (c0 + 1 > rowA + 8) s[nf][3] = -CUDART_INF_F;
            }
            mxA = fmaxf(mxA, fmaxf(s[nf][0], s[nf][1]));
            mxB = fmaxf(mxB, fmaxf(s[nf][2], s[nf][3]));
        }
        mxA = fmaxf(mxA, __shfl_xor_sync(0xffffffffu, mxA, 1));
        mxA = fmaxf(mxA, __shfl_xor_sync(0xffffffffu, mxA, 2));
        mxB = fmaxf(mxB, __shfl_xor_sync(0xffffffffu, mxB, 1));
        mxB = fmaxf(mxB, __shfl_xor_sync(0xffffffffu, mxB, 2));

        const float mAn = fmaxf(mA, mxA);
        const float mBn = fmaxf(mB, mxB);
        const float cA = ex2(mA - mAn);
        const float cB = ex2(mB - mBn);
        mA = mAn; mB = mBn;

        float sA = 0.f, sB = 0.f;
#pragma unroll
        for (int nf = 0; nf < 8; nf++) {
            s[nf][0] = ex2(s[nf][0] - mA); sA += s[nf][0];
            s[nf][1] = ex2(s[nf][1] - mA); sA += s[nf][1];
            s[nf][2] = ex2(s[nf][2] - mB); sB += s[nf][2];
            s[nf][3] = ex2(s[nf][3] - mB); sB += s[nf][3];
        }
        sA += __shfl_xor_sync(0xffffffffu, sA, 1);
        sA += __shfl_xor_sync(0xffffffffu, sA, 2);
        sB += __shfl_xor_sync(0xffffffffu, sB, 1);
        sB += __shfl_xor_sync(0xffffffffu, sB, 2);
        lA = lA * cA + sA;
        lB = lB * cB + sB;
#pragma unroll
        for (int nf = 0; nf < 8; nf++) {
            o[nf][0] *= cA; o[nf][1] *= cA;
            o[nf][2] *= cB; o[nf][3] *= cB;
        }

        // ---- O += P @ V (P frags = packs of S; V via ldmatrix.trans) ----
#pragma unroll
        for (int ksV = 0; ksV < 4; ksV++) {
            uint32_t pa[4];
            pa[0] = packh2(s[2 * ksV][0], s[2 * ksV][1]);
            pa[1] = packh2(s[2 * ksV][2], s[2 * ksV][3]);
            pa[2] = packh2(s[2 * ksV + 1][0], s[2 * ksV + 1][1]);
            pa[3] = packh2(s[2 * ksV + 1][2], s[2 * ksV + 1][3]);
#pragma unroll
            for (int nfp = 0; nfp < 4; nfp++) {
                const uint32_t ecx = (uint32_t)(((2 * nfp + lhi) ^ l7) << 4);
                uint32_t r0, r1, r2, r3;
                LDSM_X4_T(r0, r1, r2, r3, vst + vb0 + ksV * 2048 + ecx);
                uint32_t b0[2] = {r0, r1};
                uint32_t b1[2] = {r2, r3};
                mma_f16(o[2 * nfp], pa, b0);
                mma_f16(o[2 * nfp + 1], pa, b1);
            }
        }

        // ---- prefetch tile ti+2 into the stage freed at the last barrier ----
        if (ti + 2 < ntiles) {
            int ls = st + 2;
            if (ls >= 3) ls -= 3;
            load_stage(ls, ti + 2);
        }
        CP_COMMIT();
        st = (st == 2) ? 0 : st + 1;
    }

    // ---- epilogue: y = O / l -> g_yh (fp16) ----
    const float iA = 1.f / lA;
    const float iB = 1.f / lB;
    const int trA = i0 + w * 16 + (lane >> 2);
    const int ec = 2 * (lane & 3);
    uint32_t* yh = (uint32_t*)g_yh;
#pragma unroll
    for (int nf = 0; nf < 8; nf++) {
        const int e = nf * 8 + ec;
        const size_t iA2 = (((size_t)b * cfg::T + trA) * cfg::C + h * 64 + e) >> 1;
        const size_t iB2 = (((size_t)b * cfg::T + trA + 8) * cfg::C + h * 64 + e) >> 1;
        yh[iA2] = packh2(o[nf][0] * iA, o[nf][1] * iA);
        yh[iB2] = packh2(o[nf][2] * iB, o[nf][3] * iB);
    }
}

// ---------------------------------------------------------------------------
extern "C" void kernel_launch(void* const* d_in, const int* in_sizes, int n_in,
                              void* d_out, int out_size) {
    const float* x     = (const float*)d_in[0];
    const float* kcch  = (const float*)d_in[1];
    const float* vcch  = (const float*)d_in[2];
    const float* Wqkv  = (const float*)d_in[3];
    const float* bqkv  = (const float*)d_in[4];
    const float* Wproj = (const float*)d_in[5];
    const float* bproj = (const float*)d_in[6];
    float* out = (float*)d_out;

    cudaFuncSetAttribute(gemm_cp<cfg::NQKV, 0>,
                         cudaFuncAttributeMaxDynamicSharedMemorySize, GS_SMEM_BYTES);
    cudaFuncSetAttribute(gemm_cp<cfg::C, 1>,
                         cudaFuncAttributeMaxDynamicSharedMemorySize, GS_SMEM_BYTES);
    cudaFuncSetAttribute(attn_mma,
                         cudaFuncAttributeMaxDynamicSharedMemorySize, AT_SMEM_BYTES);

    // 0) fp32 -> fp16 operand conversion (x, weights, KV cache)
    cvt16<0><<<cfg::M * cfg::C / 1024, 256>>>(x);
    cvt16<1><<<cfg::C * cfg::NQKV / 1024, 256>>>(Wqkv);
    cvt16<2><<<cfg::C * cfg::C / 1024, 256>>>(Wproj);
    cvt16<3><<<cfg::B * cfg::H * cfg::L * cfg::E / 1024, 256>>>(kcch);
    cvt16<4><<<cfg::B * cfg::H * cfg::L * cfg::E / 1024, 256>>>(vcch);

    // 1) QKV projection + head split (fp16 out)
    gemm_cp<cfg::NQKV, 0><<<dim3(cfg::NQKV / 128, cfg::M / 128), 256,
                            GS_SMEM_BYTES>>>(bqkv, nullptr);

    // 2) Flash attention (cp.async + ldmatrix, fp16)
    attn_mma<<<dim3(cfg::T / 128, cfg::H, cfg::B), 256, AT_SMEM_BYTES>>>();

    // 3) Output projection
    gemm_cp<cfg::C, 1><<<dim3(cfg::C / 128, cfg::M / 128), 256,
                         GS_SMEM_BYTES>>>(bproj, out);
}

// round 13
// speedup vs baseline: 7.2252x; 1.0187x over previous
#include <cuda_runtime.h>
#include <cuda_fp16.h>
#include <math_constants.h>
#include <cstdint>
#include <cstddef>

// Problem constants
namespace cfg {
constexpr int B = 8, T = 512, C = 1024, H = 16, E = 64, L = 2048;
constexpr int M = B * T;        // 4096 rows for both GEMMs
constexpr int NQKV = 3 * C;     // 3072
constexpr int NCT = L / 64;     // 32 cache key-tiles
}

// Scratch (device globals — no allocation allowed); all operands fp16
__device__ __half g_xh[cfg::M * cfg::C];                   // x
__device__ __half g_wqkvh[cfg::C * cfg::NQKV];             // Wqkv [K][N]
__device__ __half g_wprojh[cfg::C * cfg::C];               // Wproj [K][N]
__device__ __half g_qh[cfg::B * cfg::H * cfg::T * cfg::E]; // q (B,H,T,E)
__device__ __half g_kh[cfg::B * cfg::H * cfg::T * cfg::E]; // new k
__device__ __half g_vh[cfg::B * cfg::H * cfg::T * cfg::E]; // new v
__device__ __half g_kch[cfg::B * cfg::H * cfg::L * cfg::E];// k cache fp16
__device__ __half g_vch[cfg::B * cfg::H * cfg::L * cfg::E];// v cache fp16
__device__ __half g_yh[cfg::M * cfg::C];                   // attention out

// ---------------------------------------------------------------------------
// helpers
// ---------------------------------------------------------------------------
__device__ __forceinline__ uint32_t packh2(float lo, float hi) {
    __half2 h = __floats2half2_rn(lo, hi);
    return *(uint32_t*)&h;
}

__device__ __forceinline__ uint32_t hmul2u(uint32_t x, __half2 s) {
    __half2 v = *(__half2*)&x;
    v = __hmul2(v, s);
    return *(uint32_t*)&v;
}

__device__ __forceinline__ float ex2(float x) {
    float y;
    asm("ex2.approx.ftz.f32 %0, %1;" : "=f"(y) : "f"(x));
    return y;
}

// exp2 of a pair in fp16 via one MUFU op: pack (a,b) to half2, ex2.f16x2.
__device__ __forceinline__ uint32_t ex2pack(float a, float b) {
    uint32_t h = packh2(a, b);
    uint32_t r;
    asm("ex2.approx.f16x2 %0, %1;" : "=r"(r) : "r"(h));
    return r;
}

__device__ __forceinline__ uint32_t smem_u32(const void* p) {
    uint32_t a;
    asm("{ .reg .u64 t; cvta.to.shared.u64 t, %1; cvt.u32.u64 %0, t; }"
        : "=r"(a) : "l"(p));
    return a;
}

// D(16x8,f32) += A(16x16,f16) * B(16x8,f16)
__device__ __forceinline__ void mma_f16(float* d, const uint32_t* a,
                                        const uint32_t* b) {
    asm volatile(
        "mma.sync.aligned.m16n8k16.row.col.f32.f16.f16.f32 "
        "{%0,%1,%2,%3}, {%4,%5,%6,%7}, {%8,%9}, {%0,%1,%2,%3};"
        : "+f"(d[0]), "+f"(d[1]), "+f"(d[2]), "+f"(d[3])
        : "r"(a[0]), "r"(a[1]), "r"(a[2]), "r"(a[3]), "r"(b[0]), "r"(b[1]));
}

#define CP16(dst, gsrc) \
    asm volatile("cp.async.cg.shared.global [%0], [%1], 16;" \
                 :: "r"(dst), "l"(gsrc) : "memory")
#define CP_COMMIT() asm volatile("cp.async.commit_group;" ::: "memory")
#define CP_WAIT2()  asm volatile("cp.async.wait_group 2;" ::: "memory")
#define CP_WAIT1()  asm volatile("cp.async.wait_group 1;" ::: "memory")

#define LDSM_X4(r0, r1, r2, r3, addr) \
    asm volatile("ldmatrix.sync.aligned.m8n8.x4.shared.b16 {%0,%1,%2,%3}, [%4];" \
                 : "=r"(r0), "=r"(r1), "=r"(r2), "=r"(r3) : "r"(addr))
#define LDSM_X4_T(r0, r1, r2, r3, addr) \
    asm volatile("ldmatrix.sync.aligned.m8n8.x4.trans.shared.b16 {%0,%1,%2,%3}, [%4];" \
                 : "=r"(r0), "=r"(r1), "=r"(r2), "=r"(r3) : "r"(addr))

// ---------------------------------------------------------------------------
// fp32 -> fp16 convert kernels (streaming)
// ---------------------------------------------------------------------------
template <int WHICH>
__global__ __launch_bounds__(256) void cvt16(const float* __restrict__ src) {
    __half* dst = (WHICH == 0) ? g_xh
                : (WHICH == 1) ? g_wqkvh
                : (WHICH == 2) ? g_wprojh
                : (WHICH == 3) ? g_kch : g_vch;
    const int i = blockIdx.x * 256 + threadIdx.x;
    const float4 v = ((const float4*)src)[i];
    uint32_t* d = (uint32_t*)dst;
    d[2 * i + 0] = packh2(v.x, v.y);
    d[2 * i + 1] = packh2(v.z, v.w);
}

// ---------------------------------------------------------------------------
// fp16 GEMM, cp.async 4-stage + ldmatrix (validated R11/R12). 128x128, BK=32.
// MODE 0: out = x @ Wqkv + b -> scatter fp16 to g_qh/g_kh/g_vh (B,H,T,E)
// MODE 1: out = y @ Wproj + b -> dense fp32 `out`
// ---------------------------------------------------------------------------
constexpr int GS_STAGE = 18432;
constexpr int GS_BOFF = 10240;
constexpr int GS_SMEM_BYTES = 4 * GS_STAGE + 512;   // 74240

template <int N, int MODE>
__global__ __launch_bounds__(256, 2) void gemm_cp(const float* __restrict__ bias,
                                                  float* __restrict__ out) {
    extern __shared__ uint32_t sh[];
    float* biasS = (float*)((char*)sh + 4 * GS_STAGE);

    const int t = threadIdx.x;
    const int lane = t & 31;
    const int wid = t >> 5;
    const int wm = wid >> 2;
    const int wn = wid & 3;
    const int m0 = blockIdx.y * 128;
    const int n0 = blockIdx.x * 128;

    const __half* Ab = (MODE == 1) ? g_yh : g_xh;
    const __half* Wh = (MODE == 1) ? g_wprojh : g_wqkvh;
    if (t < 128) biasS[t] = bias[n0 + t];

    const uint32_t sbase = smem_u32(sh);

    const uint32_t asd = sbase + (t >> 1) * 80 + (t & 1) * 32;
    const __half* agp = Ab + (size_t)(m0 + (t >> 1)) * cfg::C + (t & 1) * 16;
    const int bk = t >> 3;
    const int bj0 = (t & 7) * 2;
    const uint32_t bsd0 = sbase + GS_BOFF + bk * 256 + ((bj0) ^ (bk & 7)) * 16;
    const uint32_t bsd1 = sbase + GS_BOFF + bk * 256 + ((bj0 + 1) ^ (bk & 7)) * 16;
    const __half* bgp = Wh + (size_t)bk * N + n0 + bj0 * 8;

    uint64_t agg, bgg;
    asm("cvta.to.global.u64 %0, %1;" : "=l"(agg) : "l"(agp));
    asm("cvta.to.global.u64 %0, %1;" : "=l"(bgg) : "l"(bgp));

    auto load_stage = [&](int stage, int ck) {
        const uint32_t so = stage * GS_STAGE;
        const uint64_t ga = agg + (uint64_t)ck * 64;
        CP16(asd + so, ga);
        CP16(asd + so + 16, ga + 16);
        const uint64_t gb = bgg + (uint64_t)ck * 32 * N * 2;
        CP16(bsd0 + so, gb);
        CP16(bsd1 + so, gb + 16);
    };

    const int l7 = lane & 7;
    const int lm = (lane >> 3) & 1;
    const int lh = lane >> 4;
    const uint32_t aoff = sbase + (wm * 64 + l7 + 8 * lm) * 80 + lh * 16;
    const uint32_t boff = sbase + GS_BOFF + (l7 + 8 * lm) * 256;
    const uint32_t jx0 = (uint32_t)(((wn * 4 + 0 + lh) ^ l7) * 16);
    const uint32_t jx1 = (uint32_t)(((wn * 4 + 2 + lh) ^ l7) * 16);

    float acc[4][4][4];
#pragma unroll
    for (int im = 0; im < 4; im++)
#pragma unroll
        for (int in = 0; in < 4; in++)
#pragma unroll
            for (int k = 0; k < 4; k++) acc[im][in][k] = 0.f;

    auto compute = [&](int stage) {
        const uint32_t so = stage * GS_STAGE;
#pragma unroll
        for (int ks = 0; ks < 2; ks++) {
            uint32_t a[4][4];
#pragma unroll
            for (int mf = 0; mf < 4; mf++)
                LDSM_X4(a[mf][0], a[mf][1], a[mf][2], a[mf][3],
                        aoff + so + mf * 1280 + ks * 32);
            uint32_t bb[4][2];
            {
                uint32_t r0, r1, r2, r3;
                LDSM_X4_T(r0, r1, r2, r3, boff + so + ks * 4096 + jx0);
                bb[0][0] = r0; bb[0][1] = r1; bb[1][0] = r2; bb[1][1] = r3;
                LDSM_X4_T(r0, r1, r2, r3, boff + so + ks * 4096 + jx1);
                bb[2][0] = r0; bb[2][1] = r1; bb[3][0] = r2; bb[3][1] = r3;
            }
#pragma unroll
            for (int mf = 0; mf < 4; mf++)
#pragma unroll
                for (int in = 0; in < 4; in++)
                    mma_f16(acc[mf][in], a[mf], bb[in]);
        }
    };

    load_stage(0, 0); CP_COMMIT();
    load_stage(1, 1); CP_COMMIT();
    load_stage(2, 2); CP_COMMIT();

    for (int ck = 0; ck < 32; ck++) {
        CP_WAIT2();
        __syncthreads();
        compute(ck & 3);
        if (ck + 3 < 32) load_stage((ck + 3) & 3, ck + 3);
        CP_COMMIT();
    }

    const int rbase = lane >> 2;
    const int cpair = (lane & 3) * 2;

    if (MODE == 0) {
        const int sel = n0 >> 10;
        __half* dstbuf = (sel == 0) ? g_qh : (sel == 1) ? g_kh : g_vh;
#pragma unroll
        for (int im = 0; im < 4; im++) {
            const int mrow = m0 + (wm * 4 + im) * 16 + rbase;
#pragma unroll
            for (int in = 0; in < 4; in++) {
                const int nloc = (wn * 4 + in) * 8 + cpair;
                const int lc = (n0 & 1023) + nloc;
                const int h = lc >> 6;
                const int e = lc & 63;
                const float bx = biasS[nloc], by = biasS[nloc + 1];
#pragma unroll
                for (int rr = 0; rr < 2; rr++) {
                    const int m = mrow + rr * 8;
                    const int b = m >> 9;
                    const int tt = m & 511;
                    *(uint32_t*)&dstbuf[(((size_t)(b * cfg::H + h) * cfg::T) + tt) *
                                            cfg::E + e] =
                        packh2(acc[im][in][rr * 2 + 0] + bx,
                               acc[im][in][rr * 2 + 1] + by);
                }
            }
        }
    } else {
#pragma unroll
        for (int im = 0; im < 4; im++) {
            const int mrow = m0 + (wm * 4 + im) * 16 + rbase;
#pragma unroll
            for (int in = 0; in < 4; in++) {
                const int nloc = (wn * 4 + in) * 8 + cpair;
                const float bx = biasS[nloc], by = biasS[nloc + 1];
#pragma unroll
                for (int rr = 0; rr < 2; rr++) {
                    const int m = mrow + rr * 8;
                    float2 v;
                    v.x = acc[im][in][rr * 2 + 0] + bx;
                    v.y = acc[im][in][rr * 2 + 1] + by;
                    *(float2*)&out[(size_t)m * cfg::C + n0 + nloc] = v;
                }
            }
        }
    }
}

// ---------------------------------------------------------------------------
// Flash attention, fp16 mma + cp.async (3-stage) + ldmatrix (R12 structure).
// R13 deltas: P via ex2.approx.f16x2 (MUFU halved); row-sum l computed by an
// extra mma against an all-ones B fragment (kills 32 FADD + 8 SHFL per
// thread-tile); masked scores use -60 (fp16-safe -> exp 0); grid reversed so
// the heaviest q-tiles (qt=3, 40 key-tiles) schedule in wave 1.
// ---------------------------------------------------------------------------
constexpr int AT_STAGE = 16384;
constexpr int AT_SMEM_BYTES = 3 * AT_STAGE;   // 49152

__global__ __launch_bounds__(256, 2) void attn_mma() {
    extern __shared__ uint32_t sh[];
    const uint32_t sbase = smem_u32(sh);
    const int t = threadIdx.x;
    const int lane = t & 31;
    const int w = t >> 5;
    const int qt = (int)gridDim.x - 1 - (int)blockIdx.x;   // heavy tiles first
    const int h = blockIdx.y;
    const int b = blockIdx.z;
    const int i0 = qt * 128;

    const size_t bh = (size_t)b * cfg::H + h;

    // ---- Q fragments (fp16 direct), scale*log2e folded ----
    uint32_t qf[4][4];
    {
        const __half2 hs = __float2half2_rn(0.125f * 1.44269504f);
        const int r = w * 16 + (lane >> 2);
        const int lq = lane & 3;
        const uint32_t* q0 = (const uint32_t*)g_qh + (bh * cfg::T + i0 + r) * 32;
        const uint32_t* q8 = q0 + 8 * 32;
#pragma unroll
        for (int ks = 0; ks < 4; ks++) {
            qf[ks][0] = hmul2u(q0[8 * ks + lq], hs);
            qf[ks][1] = hmul2u(q8[8 * ks + lq], hs);
            qf[ks][2] = hmul2u(q0[8 * ks + 4 + lq], hs);
            qf[ks][3] = hmul2u(q8[8 * ks + 4 + lq], hs);
        }
    }

    // ---- cp.async loader: thread covers (key kr, e-chunks ec0, ec0+1) ----
    const int kr = t >> 2;
    const int ec0 = (t & 3) * 2;
    const uint32_t ksm0 = (uint32_t)(kr * 128 + ((ec0 ^ (kr & 7)) << 4));
    const uint32_t ksm1 = (uint32_t)(kr * 128 + (((ec0 + 1) ^ (kr & 7)) << 4));
    const uint64_t goff = (uint64_t)kr * 128 + (uint64_t)ec0 * 16;
    const uint64_t gkc = (uint64_t)__cvta_generic_to_global(g_kch) + bh * 262144 + goff;
    const uint64_t gvc = (uint64_t)__cvta_generic_to_global(g_vch) + bh * 262144 + goff;
    const uint64_t gkn = (uint64_t)__cvta_generic_to_global(g_kh) + bh * 65536 + goff;
    const uint64_t gvn = (uint64_t)__cvta_generic_to_global(g_vh) + bh * 65536 + goff;

    auto load_stage = [&](int st, int ti) {
        uint64_t gk, gv;
        if (ti < cfg::NCT) {
            gk = gkc + (uint64_t)ti * 8192;
            gv = gvc + (uint64_t)ti * 8192;
        } else {
            gk = gkn + (uint64_t)(ti - cfg::NCT) * 8192;
            gv = gvn + (uint64_t)(ti - cfg::NCT) * 8192;
        }
        const uint32_t sb = sbase + st * AT_STAGE;
        CP16(sb + ksm0, gk);
        CP16(sb + ksm1, gk + 16);
        CP16(sb + 8192 + ksm0, gv);
        CP16(sb + 8192 + ksm1, gv + 16);
    };

    // ---- ldmatrix per-lane address components ----
    const int l7 = lane & 7;
    const int lmid = (lane >> 3) & 1;
    const int lhi = lane >> 4;
    const uint32_t kb0 = (uint32_t)((lhi * 8 + l7) * 128);
    const uint32_t vb0 = (uint32_t)((lmid * 8 + l7) * 128);

    float o[8][4];
#pragma unroll
    for (int nf = 0; nf < 8; nf++)
#pragma unroll
        for (int r = 0; r < 4; r++) o[nf][r] = 0.f;
    float lacc[4] = {0.f, 0.f, 0.f, 0.f};      // row-sum accumulator via mma
    float mA = -CUDART_INF_F, mB = -CUDART_INF_F;

    const uint32_t ones2 = 0x3C003C00u;        // half2(1.0, 1.0)
    uint32_t onesb[2] = {ones2, ones2};

    const int ntiles = 34 + 2 * qt;

    load_stage(0, 0); CP_COMMIT();
    load_stage(1, 1); CP_COMMIT();

    int st = 0;
    for (int ti = 0; ti < ntiles; ti++) {
        CP_WAIT1();
        __syncthreads();
        const uint32_t kst = sbase + st * AT_STAGE;
        const uint32_t vst = kst + 8192;

        // ---- S = Q @ K^T (log2-scaled) ----
        float s[8][4];
#pragma unroll
        for (int nf = 0; nf < 8; nf++)
#pragma unroll
            for (int r = 0; r < 4; r++) s[nf][r] = 0.f;
#pragma unroll
        for (int ks = 0; ks < 4; ks++) {
            const uint32_t ecx = (uint32_t)(((2 * ks + lmid) ^ l7) << 4);
#pragma unroll
            for (int nfp = 0; nfp < 4; nfp++) {
                uint32_t r0, r1, r2, r3;
                LDSM_X4(r0, r1, r2, r3, kst + kb0 + nfp * 2048 + ecx);
                uint32_t b0[2] = {r0, r1};
                uint32_t b1[2] = {r2, r3};
                mma_f16(s[2 * nfp], qf[ks], b0);
                mma_f16(s[2 * nfp + 1], qf[ks], b1);
            }
        }

        // ---- mask + running max ----
        const bool diag = (ti >= cfg::NCT + 2 * qt);
        const int rowA = i0 + w * 16 + (lane >> 2);
        const int colb = (ti - cfg::NCT) * 64 + 2 * (lane & 3);
        float mxA = -CUDART_INF_F, mxB = -CUDART_INF_F;
#pragma unroll
        for (int nf = 0; nf < 8; nf++) {
            if (diag) {
                const int c0 = colb + nf * 8;
                if (c0 > rowA) s[nf][0] = -60.f;
                if (c0 + 1 > rowA) s[nf][1] = -60.f;
                if (c0 > rowA + 8) s[nf][2] = -60.f;
                if (c0 + 1 > rowA + 8) s[nf][3] = -60.f;
            }
            mxA = fmaxf(mxA, fmaxf(s[nf][0], s[nf][1]));
            mxB = fmaxf(mxB, fmaxf(s[nf][2], s[nf][3]));
        }
        mxA = fmaxf(mxA, __shfl_xor_sync(0xffffffffu, mxA, 1));
        mxA = fmaxf(mxA, __shfl_xor_sync(0xffffffffu, mxA, 2));
        mxB = fmaxf(mxB, __shfl_xor_sync(0xffffffffu, mxB, 1));
        mxB = fmaxf(mxB, __shfl_xor_sync(0xffffffffu, mxB, 2));

        const float mAn = fmaxf(mA, mxA);
        const float mBn = fmaxf(mB, mxB);
        const float cA = ex2(mA - mAn);
        const float cB = ex2(mB - mBn);
        mA = mAn; mB = mBn;

        // rescale O and l
#pragma unroll
        for (int nf = 0; nf < 8; nf++) {
            o[nf][0] *= cA; o[nf][1] *= cA;
            o[nf][2] *= cB; o[nf][3] *= cB;
        }
        lacc[0] *= cA; lacc[2] *= cB;

        // ---- P = exp2(s - m) in fp16; O += P @ V; l += P @ 1 ----
#pragma unroll
        for (int ksV = 0; ksV < 4; ksV++) {
            uint32_t pa[4];
            pa[0] = ex2pack(s[2 * ksV][0] - mA, s[2 * ksV][1] - mA);
            pa[1] = ex2pack(s[2 * ksV][2] - mB, s[2 * ksV][3] - mB);
            pa[2] = ex2pack(s[2 * ksV + 1][0] - mA, s[2 * ksV + 1][1] - mA);
            pa[3] = ex2pack(s[2 * ksV + 1][2] - mB, s[2 * ksV + 1][3] - mB);
            mma_f16(lacc, pa, onesb);
#pragma unroll
            for (int nfp = 0; nfp < 4; nfp++) {
                const uint32_t ecx = (uint32_t)(((2 * nfp + lhi) ^ l7) << 4);
                uint32_t r0, r1, r2, r3;
                LDSM_X4_T(r0, r1, r2, r3, vst + vb0 + ksV * 2048 + ecx);
                uint32_t b0[2] = {r0, r1};
                uint32_t b1[2] = {r2, r3};
                mma_f16(o[2 * nfp], pa, b0);
                mma_f16(o[2 * nfp + 1], pa, b1);
            }
        }

        // ---- prefetch tile ti+2 into the stage freed at the last barrier ----
        if (ti + 2 < ntiles) {
            int ls = st + 2;
            if (ls >= 3) ls -= 3;
            load_stage(ls, ti + 2);
        }
        CP_COMMIT();
        st = (st == 2) ? 0 : st + 1;
    }

    // ---- epilogue: y = O / l -> g_yh (fp16) ----
    const float iA = 1.f / lacc[0];
    const float iB = 1.f / lacc[2];
    const int trA = i0 + w * 16 + (lane >> 2);
    const int ec = 2 * (lane & 3);
    uint32_t* yh = (uint32_t*)g_yh;
#pragma unroll
    for (int nf = 0; nf < 8; nf++) {
        const int e = nf * 8 + ec;
        const size_t iA2 = (((size_t)b * cfg::T + trA) * cfg::C + h * 64 + e) >> 1;
        const size_t iB2 = (((size_t)b * cfg::T + trA + 8) * cfg::C + h * 64 + e) >> 1;
        yh[iA2] = packh2(o[nf][0] * iA, o[nf][1] * iA);
        yh[iB2] = packh2(o[nf][2] * iB, o[nf][3] * iB);
    }
}

// ---------------------------------------------------------------------------
extern "C" void kernel_launch(void* const* d_in, const int* in_sizes, int n_in,
                              void* d_out, int out_size) {
    const float* x     = (const float*)d_in[0];
    const float* kcch  = (const float*)d_in[1];
    const float* vcch  = (const float*)d_in[2];
    const float* Wqkv  = (const float*)d_in[3];
    const float* bqkv  = (const float*)d_in[4];
    const float* Wproj = (const float*)d_in[5];
    const float* bproj = (const float*)d_in[6];
    float* out = (float*)d_out;

    cudaFuncSetAttribute(gemm_cp<cfg::NQKV, 0>,
                         cudaFuncAttributeMaxDynamicSharedMemorySize, GS_SMEM_BYTES);
    cudaFuncSetAttribute(gemm_cp<cfg::C, 1>,
                         cudaFuncAttributeMaxDynamicSharedMemorySize, GS_SMEM_BYTES);
    cudaFuncSetAttribute(attn_mma,
                         cudaFuncAttributeMaxDynamicSharedMemorySize, AT_SMEM_BYTES);

    // 0) fp32 -> fp16 operand conversion (x, weights, KV cache)
    cvt16<0><<<cfg::M * cfg::C / 1024, 256>>>(x);
    cvt16<1><<<cfg::C * cfg::NQKV / 1024, 256>>>(Wqkv);
    cvt16<2><<<cfg::C * cfg::C / 1024, 256>>>(Wproj);
    cvt16<3><<<cfg::B * cfg::H * cfg::L * cfg::E / 1024, 256>>>(kcch);
    cvt16<4><<<cfg::B * cfg::H * cfg::L * cfg::E / 1024, 256>>>(vcch);

    // 1) QKV projection + head split (fp16 out)
    gemm_cp<cfg::NQKV, 0><<<dim3(cfg::NQKV / 128, cfg::M / 128), 256,
                            GS_SMEM_BYTES>>>(bqkv, nullptr);

    // 2) Flash attention (cp.async + ldmatrix, fp16, l-via-mma)
    attn_mma<<<dim3(cfg::T / 128, cfg::H, cfg::B), 256, AT_SMEM_BYTES>>>();

    // 3) Output projection
    gemm_cp<cfg::C, 1><<<dim3(cfg::C / 128, cfg::M / 128), 256,
                         GS_SMEM_BYTES>>>(bproj, out);
}

// round 16
// speedup vs baseline: 7.6768x; 1.0625x over previous
#include <cuda_runtime.h>
#include <cuda_fp16.h>
#include <math_constants.h>
#include <cstdint>
#include <cstddef>

// Problem constants
namespace cfg {
constexpr int B = 8, T = 512, C = 1024, H = 16, E = 64, L = 2048;
constexpr int M = B * T;        // 4096 rows for both GEMMs
constexpr int NQKV = 3 * C;     // 3072
constexpr int NCT = L / 64;     // 32 cache key-tiles
}

// Scratch (device globals — no allocation allowed); all operands fp16
__device__ __half g_xh[cfg::M * cfg::C];                   // x
__device__ __half g_wqkvh[cfg::C * cfg::NQKV];             // Wqkv [K][N]
__device__ __half g_wprojh[cfg::C * cfg::C];               // Wproj [K][N]
__device__ __half g_qh[cfg::B * cfg::H * cfg::T * cfg::E]; // q (B,H,T,E)
__device__ __half g_kh[cfg::B * cfg::H * cfg::T * cfg::E]; // new k
__device__ __half g_vh[cfg::B * cfg::H * cfg::T * cfg::E]; // new v
__device__ __half g_kch[cfg::B * cfg::H * cfg::L * cfg::E];// k cache fp16
__device__ __half g_vch[cfg::B * cfg::H * cfg::L * cfg::E];// v cache fp16
__device__ __half g_yh[cfg::M * cfg::C];                   // attention out

// ---------------------------------------------------------------------------
// helpers
// ---------------------------------------------------------------------------
__device__ __forceinline__ uint32_t packh2(float lo, float hi) {
    __half2 h = __floats2half2_rn(lo, hi);
    return *(uint32_t*)&h;
}

__device__ __forceinline__ uint32_t hmul2u(uint32_t x, __half2 s) {
    __half2 v = *(__half2*)&x;
    v = __hmul2(v, s);
    return *(uint32_t*)&v;
}

__device__ __forceinline__ float ex2(float x) {
    float y;
    asm("ex2.approx.ftz.f32 %0, %1;" : "=f"(y) : "f"(x));
    return y;
}

// exp2 of a pair in fp16 via one MUFU op
__device__ __forceinline__ uint32_t ex2pack(float a, float b) {
    uint32_t h = packh2(a, b);
    uint32_t r;
    asm("ex2.approx.f16x2 %0, %1;" : "=r"(r) : "r"(h));
    return r;
}

__device__ __forceinline__ uint32_t smem_u32(const void* p) {
    uint32_t a;
    asm("{ .reg .u64 t; cvta.to.shared.u64 t, %1; cvt.u32.u64 %0, t; }"
        : "=r"(a) : "l"(p));
    return a;
}

// D(16x8,f32) += A(16x16,f16) * B(16x8,f16)
__device__ __forceinline__ void mma_f16(float* d, const uint32_t* a,
                                        const uint32_t* b) {
    asm volatile(
        "mma.sync.aligned.m16n8k16.row.col.f32.f16.f16.f32 "
        "{%0,%1,%2,%3}, {%4,%5,%6,%7}, {%8,%9}, {%0,%1,%2,%3};"
        : "+f"(d[0]), "+f"(d[1]), "+f"(d[2]), "+f"(d[3])
        : "r"(a[0]), "r"(a[1]), "r"(a[2]), "r"(a[3]), "r"(b[0]), "r"(b[1]));
}

#define CP16(dst, gsrc) \
    asm volatile("cp.async.cg.shared.global [%0], [%1], 16;" \
                 :: "r"(dst), "l"(gsrc) : "memory")
#define CP_COMMIT() asm volatile("cp.async.commit_group;" ::: "memory")
#define CP_WAIT2()  asm volatile("cp.async.wait_group 2;" ::: "memory")
#define CP_WAIT1()  asm volatile("cp.async.wait_group 1;" ::: "memory")

#define LDSM_X4(r0, r1, r2, r3, addr) \
    asm volatile("ldmatrix.sync.aligned.m8n8.x4.shared.b16 {%0,%1,%2,%3}, [%4];" \
                 : "=r"(r0), "=r"(r1), "=r"(r2), "=r"(r3) : "r"(addr))
#define LDSM_X4_T(r0, r1, r2, r3, addr) \
    asm volatile("ldmatrix.sync.aligned.m8n8.x4.trans.shared.b16 {%0,%1,%2,%3}, [%4];" \
                 : "=r"(r0), "=r"(r1), "=r"(r2), "=r"(r3) : "r"(addr))

// ---------------------------------------------------------------------------
// Pre-convert: x and Wqkv to fp16, one launch.
// float4 counts: x = 1,048,576; wqkv = 786,432; total 1,835,008 = 1792*1024.
// ---------------------------------------------------------------------------
__global__ __launch_bounds__(256) void cvt_pre(const float* __restrict__ x,
                                               const float* __restrict__ wqkv) {
    constexpr uint32_t XN = 1048576u;
    const uint32_t base = blockIdx.x * 1024u + threadIdx.x;
#pragma unroll
    for (int j = 0; j < 4; j++) {
        const uint32_t gi = base + j * 256u;
        const float4* src;
        uint2* dst;
        uint32_t idx;
        if (gi < XN) { src = (const float4*)x; dst = (uint2*)g_xh; idx = gi; }
        else { src = (const float4*)wqkv; dst = (uint2*)g_wqkvh; idx = gi - XN; }
        const float4 v = src[idx];
        uint2 o;
        o.x = packh2(v.x, v.y);
        o.y = packh2(v.z, v.w);
        dst[idx] = o;
    }
}

// ---------------------------------------------------------------------------
// fp16 GEMM, cp.async 4-stage + ldmatrix (validated R11-R13). 128x128, BK=32.
// MODE 0: out = x @ Wqkv + b -> scatter fp16 to g_qh/g_kh/g_vh (B,H,T,E);
//         ALSO strip-mines the kcache/vcache/Wproj fp32->fp16 conversion
//         through its mainloop (2 float4/thread/iter; loads issued early,
//         stores after commit) — hides the 3 convert passes in GEMM slack.
// MODE 1: out = y @ Wproj + b -> dense fp32 `out`
// ---------------------------------------------------------------------------
constexpr int GS_STAGE = 18432;
constexpr int GS_BOFF = 10240;
constexpr int GS_SMEM_BYTES = 4 * GS_STAGE + 512;   // 74240

// fused-cvt workload (float4 units)
constexpr uint32_t CV_KC = 4194304u;                 // kcache
constexpr uint32_t CV_KV = 8388608u;                 // + vcache
constexpr uint32_t CV_TOT = 8650752u;                // + wproj
constexpr uint32_t CV_STRIDE = 768u * 256u;          // grid threads

template <int N, int MODE>
__global__ __launch_bounds__(256, 2) void gemm_cp(const float* __restrict__ bias,
                                                  float* __restrict__ out,
                                                  const float* __restrict__ kcc,
                                                  const float* __restrict__ vcc,
                                                  const float* __restrict__ wpj) {
    extern __shared__ uint32_t sh[];
    float* biasS = (float*)((char*)sh + 4 * GS_STAGE);

    const int t = threadIdx.x;
    const int lane = t & 31;
    const int wid = t >> 5;
    const int wm = wid >> 2;
    const int wn = wid & 3;
    const int m0 = blockIdx.y * 128;
    const int n0 = blockIdx.x * 128;

    const __half* Ab = (MODE == 1) ? g_yh : g_xh;
    const __half* Wh = (MODE == 1) ? g_wprojh : g_wqkvh;
    if (t < 128) biasS[t] = bias[n0 + t];

    const uint32_t sbase = smem_u32(sh);

    const uint32_t asd = sbase + (t >> 1) * 80 + (t & 1) * 32;
    const __half* agp = Ab + (size_t)(m0 + (t >> 1)) * cfg::C + (t & 1) * 16;
    const int bk = t >> 3;
    const int bj0 = (t & 7) * 2;
    const uint32_t bsd0 = sbase + GS_BOFF + bk * 256 + ((bj0) ^ (bk & 7)) * 16;
    const uint32_t bsd1 = sbase + GS_BOFF + bk * 256 + ((bj0 + 1) ^ (bk & 7)) * 16;
    const __half* bgp = Wh + (size_t)bk * N + n0 + bj0 * 8;

    uint64_t agg, bgg;
    asm("cvta.to.global.u64 %0, %1;" : "=l"(agg) : "l"(agp));
    asm("cvta.to.global.u64 %0, %1;" : "=l"(bgg) : "l"(bgp));

    auto load_stage = [&](int stage, int ck) {
        const uint32_t so = stage * GS_STAGE;
        const uint64_t ga = agg + (uint64_t)ck * 64;
        CP16(asd + so, ga);
        CP16(asd + so + 16, ga + 16);
        const uint64_t gb = bgg + (uint64_t)ck * 32 * N * 2;
        CP16(bsd0 + so, gb);
        CP16(bsd1 + so, gb + 16);
    };

    const int l7 = lane & 7;
    const int lm = (lane >> 3) & 1;
    const int lh = lane >> 4;
    const uint32_t aoff = sbase + (wm * 64 + l7 + 8 * lm) * 80 + lh * 16;
    const uint32_t boff = sbase + GS_BOFF + (l7 + 8 * lm) * 256;
    const uint32_t jx0 = (uint32_t)(((wn * 4 + 0 + lh) ^ l7) * 16);
    const uint32_t jx1 = (uint32_t)(((wn * 4 + 2 + lh) ^ l7) * 16);

    // fused-cvt base index (MODE 0 only)
    const uint32_t cvtb =
        (uint32_t)(blockIdx.y * gridDim.x + blockIdx.x) * 256u + (uint32_t)t;

    float acc[4][4][4];
#pragma unroll
    for (int im = 0; im < 4; im++)
#pragma unroll
        for (int in = 0; in < 4; in++)
#pragma unroll
            for (int k = 0; k < 4; k++) acc[im][in][k] = 0.f;

    auto compute = [&](int stage) {
        const uint32_t so = stage * GS_STAGE;
#pragma unroll
        for (int ks = 0; ks < 2; ks++) {
            uint32_t a[4][4];
#pragma unroll
            for (int mf = 0; mf < 4; mf++)
                LDSM_X4(a[mf][0], a[mf][1], a[mf][2], a[mf][3],
                        aoff + so + mf * 1280 + ks * 32);
            uint32_t bb[4][2];
            {
                uint32_t r0, r1, r2, r3;
                LDSM_X4_T(r0, r1, r2, r3, boff + so + ks * 4096 + jx0);
                bb[0][0] = r0; bb[0][1] = r1; bb[1][0] = r2; bb[1][1] = r3;
                LDSM_X4_T(r0, r1, r2, r3, boff + so + ks * 4096 + jx1);
                bb[2][0] = r0; bb[2][1] = r1; bb[3][0] = r2; bb[3][1] = r3;
            }
#pragma unroll
            for (int mf = 0; mf < 4; mf++)
#pragma unroll
                for (int in = 0; in < 4; in++)
                    mma_f16(acc[mf][in], a[mf], bb[in]);
        }
    };

    load_stage(0, 0); CP_COMMIT();
    load_stage(1, 1); CP_COMMIT();
    load_stage(2, 2); CP_COMMIT();

    for (int ck = 0; ck < 32; ck++) {
        CP_WAIT2();
        __syncthreads();

        // ---- fused cvt: issue loads early (latency hides behind mma) ----
        float4 cv[2];
        uint2* cdst[2];
        bool cvp[2];
        if (MODE == 0) {
#pragma unroll
            for (int j = 0; j < 2; j++) {
                const uint32_t gi = (uint32_t)(ck * 2 + j) * CV_STRIDE + cvtb;
                cvp[j] = (gi < CV_TOT);
                if (cvp[j]) {
                    const float4* src;
                    uint2* dst;
                    uint32_t idx;
                    if (gi < CV_KC) {
                        src = (const float4*)kcc; dst = (uint2*)g_kch; idx = gi;
                    } else if (gi < CV_KV) {
                        src = (const float4*)vcc; dst = (uint2*)g_vch; idx = gi - CV_KC;
                    } else {
                        src = (const float4*)wpj; dst = (uint2*)g_wprojh; idx = gi - CV_KV;
                    }
                    cv[j] = src[idx];
                    cdst[j] = dst + idx;
                }
            }
        }

        compute(ck & 3);
        if (ck + 3 < 32) load_stage((ck + 3) & 3, ck + 3);
        CP_COMMIT();

        // ---- fused cvt: pack + store late ----
        if (MODE == 0) {
#pragma unroll
            for (int j = 0; j < 2; j++) {
                if (cvp[j]) {
                    uint2 o;
                    o.x = packh2(cv[j].x, cv[j].y);
                    o.y = packh2(cv[j].z, cv[j].w);
                    *cdst[j] = o;
                }
            }
        }
    }

    const int rbase = lane >> 2;
    const int cpair = (lane & 3) * 2;

    if (MODE == 0) {
        const int sel = n0 >> 10;
        __half* dstbuf = (sel == 0) ? g_qh : (sel == 1) ? g_kh : g_vh;
#pragma unroll
        for (int im = 0; im < 4; im++) {
            const int mrow = m0 + (wm * 4 + im) * 16 + rbase;
#pragma unroll
            for (int in = 0; in < 4; in++) {
                const int nloc = (wn * 4 + in) * 8 + cpair;
                const int lc = (n0 & 1023) + nloc;
                const int h = lc >> 6;
                const int e = lc & 63;
                const float bx = biasS[nloc], by = biasS[nloc + 1];
#pragma unroll
                for (int rr = 0; rr < 2; rr++) {
                    const int m = mrow + rr * 8;
                    const int b = m >> 9;
                    const int tt = m & 511;
                    *(uint32_t*)&dstbuf[(((size_t)(b * cfg::H + h) * cfg::T) + tt) *
                                            cfg::E + e] =
                        packh2(acc[im][in][rr * 2 + 0] + bx,
                               acc[im][in][rr * 2 + 1] + by);
                }
            }
        }
    } else {
#pragma unroll
        for (int im = 0; im < 4; im++) {
            const int mrow = m0 + (wm * 4 + im) * 16 + rbase;
#pragma unroll
            for (int in = 0; in < 4; in++) {
                const int nloc = (wn * 4 + in) * 8 + cpair;
                const float bx = biasS[nloc], by = biasS[nloc + 1];
#pragma unroll
                for (int rr = 0; rr < 2; rr++) {
                    const int m = mrow + rr * 8;
                    float2 v;
                    v.x = acc[im][in][rr * 2 + 0] + bx;
                    v.y = acc[im][in][rr * 2 + 1] + by;
                    *(float2*)&out[(size_t)m * cfg::C + n0 + nloc] = v;
                }
            }
        }
    }
}

// ---------------------------------------------------------------------------
// Flash attention, fp16 mma + cp.async (3-stage) + ldmatrix (R13, unchanged).
// ---------------------------------------------------------------------------
constexpr int AT_STAGE = 16384;
constexpr int AT_SMEM_BYTES = 3 * AT_STAGE;   // 49152

__global__ __launch_bounds__(256, 2) void attn_mma() {
    extern __shared__ uint32_t sh[];
    const uint32_t sbase = smem_u32(sh);
    const int t = threadIdx.x;
    const int lane = t & 31;
    const int w = t >> 5;
    const int qt = (int)gridDim.x - 1 - (int)blockIdx.x;   // heavy tiles first
    const int h = blockIdx.y;
    const int b = blockIdx.z;
    const int i0 = qt * 128;

    const size_t bh = (size_t)b * cfg::H + h;

    // ---- Q fragments (fp16 direct), scale*log2e folded ----
    uint32_t qf[4][4];
    {
        const __half2 hs = __float2half2_rn(0.125f * 1.44269504f);
        const int r = w * 16 + (lane >> 2);
        const int lq = lane & 3;
        const uint32_t* q0 = (const uint32_t*)g_qh + (bh * cfg::T + i0 + r) * 32;
        const uint32_t* q8 = q0 + 8 * 32;
#pragma unroll
        for (int ks = 0; ks < 4; ks++) {
            qf[ks][0] = hmul2u(q0[8 * ks + lq], hs);
            qf[ks][1] = hmul2u(q8[8 * ks + lq], hs);
            qf[ks][2] = hmul2u(q0[8 * ks + 4 + lq], hs);
            qf[ks][3] = hmul2u(q8[8 * ks + 4 + lq], hs);
        }
    }

    // ---- cp.async loader ----
    const int kr = t >> 2;
    const int ec0 = (t & 3) * 2;
    const uint32_t ksm0 = (uint32_t)(kr * 128 + ((ec0 ^ (kr & 7)) << 4));
    const uint32_t ksm1 = (uint32_t)(kr * 128 + (((ec0 + 1) ^ (kr & 7)) << 4));
    const uint64_t goff = (uint64_t)kr * 128 + (uint64_t)ec0 * 16;
    const uint64_t gkc = (uint64_t)__cvta_generic_to_global(g_kch) + bh * 262144 + goff;
    const uint64_t gvc = (uint64_t)__cvta_generic_to_global(g_vch) + bh * 262144 + goff;
    const uint64_t gkn = (uint64_t)__cvta_generic_to_global(g_kh) + bh * 65536 + goff;
    const uint64_t gvn = (uint64_t)__cvta_generic_to_global(g_vh) + bh * 65536 + goff;

    auto load_stage = [&](int st, int ti) {
        uint64_t gk, gv;
        if (ti < cfg::NCT) {
            gk = gkc + (uint64_t)ti * 8192;
            gv = gvc + (uint64_t)ti * 8192;
        } else {
            gk = gkn + (uint64_t)(ti - cfg::NCT) * 8192;
            gv = gvn + (uint64_t)(ti - cfg::NCT) * 8192;
        }
        const uint32_t sb = sbase + st * AT_STAGE;
        CP16(sb + ksm0, gk);
        CP16(sb + ksm1, gk + 16);
        CP16(sb + 8192 + ksm0, gv);
        CP16(sb + 8192 + ksm1, gv + 16);
    };

    const int l7 = lane & 7;
    const int lmid = (lane >> 3) & 1;
    const int lhi = lane >> 4;
    const uint32_t kb0 = (uint32_t)((lhi * 8 + l7) * 128);
    const uint32_t vb0 = (uint32_t)((lmid * 8 + l7) * 128);

    float o[8][4];
#pragma unroll
    for (int nf = 0; nf < 8; nf++)
#pragma unroll
        for (int r = 0; r < 4; r++) o[nf][r] = 0.f;
    float lacc[4] = {0.f, 0.f, 0.f, 0.f};
    float mA = -CUDART_INF_F, mB = -CUDART_INF_F;

    const uint32_t ones2 = 0x3C003C00u;
    uint32_t onesb[2] = {ones2, ones2};

    const int ntiles = 34 + 2 * qt;

    load_stage(0, 0); CP_COMMIT();
    load_stage(1, 1); CP_COMMIT();

    int st = 0;
    for (int ti = 0; ti < ntiles; ti++) {
        CP_WAIT1();
        __syncthreads();
        const uint32_t kst = sbase + st * AT_STAGE;
        const uint32_t vst = kst + 8192;

        // ---- S = Q @ K^T (log2-scaled) ----
        float s[8][4];
#pragma unroll
        for (int nf = 0; nf < 8; nf++)
#pragma unroll
            for (int r = 0; r < 4; r++) s[nf][r] = 0.f;
#pragma unroll
        for (int ks = 0; ks < 4; ks++) {
            const uint32_t ecx = (uint32_t)(((2 * ks + lmid) ^ l7) << 4);
#pragma unroll
            for (int nfp = 0; nfp < 4; nfp++) {
                uint32_t r0, r1, r2, r3;
                LDSM_X4(r0, r1, r2, r3, kst + kb0 + nfp * 2048 + ecx);
                uint32_t b0[2] = {r0, r1};
                uint32_t b1[2] = {r2, r3};
                mma_f16(s[2 * nfp], qf[ks], b0);
                mma_f16(s[2 * nfp + 1], qf[ks], b1);
            }
        }

        // ---- mask + running max ----
        const bool diag = (ti >= cfg::NCT + 2 * qt);
        const int rowA = i0 + w * 16 + (lane >> 2);
        const int colb = (ti - cfg::NCT) * 64 + 2 * (lane & 3);
        float mxA = -CUDART_INF_F, mxB = -CUDART_INF_F;
#pragma unroll
        for (int nf = 0; nf < 8; nf++) {
            if (diag) {
                const int c0 = colb + nf * 8;
                if (c0 > rowA) s[nf][0] = -60.f;
                if (c0 + 1 > rowA) s[nf][1] = -60.f;
                if (c0 > rowA + 8) s[nf][2] = -60.f;
                if (c0 + 1 > rowA + 8) s[nf][3] = -60.f;
            }
            mxA = fmaxf(mxA, fmaxf(s[nf][0], s[nf][1]));
            mxB = fmaxf(mxB, fmaxf(s[nf][2], s[nf][3]));
        }
        mxA = fmaxf(mxA, __shfl_xor_sync(0xffffffffu, mxA, 1));
        mxA = fmaxf(mxA, __shfl_xor_sync(0xffffffffu, mxA, 2));
        mxB = fmaxf(mxB, __shfl_xor_sync(0xffffffffu, mxB, 1));
        mxB = fmaxf(mxB, __shfl_xor_sync(0xffffffffu, mxB, 2));

        const float mAn = fmaxf(mA, mxA);
        const float mBn = fmaxf(mB, mxB);
        const float cA = ex2(mA - mAn);
        const float cB = ex2(mB - mBn);
        mA = mAn; mB = mBn;

#pragma unroll
        for (int nf = 0; nf < 8; nf++) {
            o[nf][0] *= cA; o[nf][1] *= cA;
            o[nf][2] *= cB; o[nf][3] *= cB;
        }
        lacc[0] *= cA; lacc[2] *= cB;

        // ---- P = exp2(s - m) fp16; O += P @ V; l += P @ 1 ----
#pragma unroll
        for (int ksV = 0; ksV < 4; ksV++) {
            uint32_t pa[4];
            pa[0] = ex2pack(s[2 * ksV][0] - mA, s[2 * ksV][1] - mA);
            pa[1] = ex2pack(s[2 * ksV][2] - mB, s[2 * ksV][3] - mB);
            pa[2] = ex2pack(s[2 * ksV + 1][0] - mA, s[2 * ksV + 1][1] - mA);
            pa[3] = ex2pack(s[2 * ksV + 1][2] - mB, s[2 * ksV + 1][3] - mB);
            mma_f16(lacc, pa, onesb);
#pragma unroll
            for (int nfp = 0; nfp < 4; nfp++) {
                const uint32_t ecx = (uint32_t)(((2 * nfp + lhi) ^ l7) << 4);
                uint32_t r0, r1, r2, r3;
                LDSM_X4_T(r0, r1, r2, r3, vst + vb0 + ksV * 2048 + ecx);
                uint32_t b0[2] = {r0, r1};
                uint32_t b1[2] = {r2, r3};
                mma_f16(o[2 * nfp], pa, b0);
                mma_f16(o[2 * nfp + 1], pa, b1);
            }
        }

        if (ti + 2 < ntiles) {
            int ls = st + 2;
            if (ls >= 3) ls -= 3;
            load_stage(ls, ti + 2);
        }
        CP_COMMIT();
        st = (st == 2) ? 0 : st + 1;
    }

    // ---- epilogue: y = O / l -> g_yh (fp16) ----
    const float iA = 1.f / lacc[0];
    const float iB = 1.f / lacc[2];
    const int trA = i0 + w * 16 + (lane >> 2);
    const int ec = 2 * (lane & 3);
    uint32_t* yh = (uint32_t*)g_yh;
#pragma unroll
    for (int nf = 0; nf < 8; nf++) {
        const int e = nf * 8 + ec;
        const size_t iA2 = (((size_t)b * cfg::T + trA) * cfg::C + h * 64 + e) >> 1;
        const size_t iB2 = (((size_t)b * cfg::T + trA + 8) * cfg::C + h * 64 + e) >> 1;
        yh[iA2] = packh2(o[nf][0] * iA, o[nf][1] * iA);
        yh[iB2] = packh2(o[nf][2] * iB, o[nf][3] * iB);
    }
}

// ---------------------------------------------------------------------------
extern "C" void kernel_launch(void* const* d_in, const int* in_sizes, int n_in,
                              void* d_out, int out_size) {
    const float* x     = (const float*)d_in[0];
    const float* kcch  = (const float*)d_in[1];
    const float* vcch  = (const float*)d_in[2];
    const float* Wqkv  = (const float*)d_in[3];
    const float* bqkv  = (const float*)d_in[4];
    const float* Wproj = (const float*)d_in[5];
    const float* bproj = (const float*)d_in[6];
    float* out = (float*)d_out;

    cudaFuncSetAttribute(gemm_cp<cfg::NQKV, 0>,
                         cudaFuncAttributeMaxDynamicSharedMemorySize, GS_SMEM_BYTES);
    cudaFuncSetAttribute(gemm_cp<cfg::C, 1>,
                         cudaFuncAttributeMaxDynamicSharedMemorySize, GS_SMEM_BYTES);
    cudaFuncSetAttribute(attn_mma,
                         cudaFuncAttributeMaxDynamicSharedMemorySize, AT_SMEM_BYTES);

    // 0) convert x + Wqkv (needed by the qkv GEMM)
    cvt_pre<<<1792, 256>>>(x, Wqkv);

    // 1) QKV projection + head split; also converts kcache/vcache/Wproj
    //    inside its mainloop slack (needed only by later launches)
    gemm_cp<cfg::NQKV, 0><<<dim3(cfg::NQKV / 128, cfg::M / 128), 256,
                            GS_SMEM_BYTES>>>(bqkv, nullptr, kcch, vcch, Wproj);

    // 2) Flash attention (cp.async + ldmatrix, fp16, l-via-mma)
    attn_mma<<<dim3(cfg::T / 128, cfg::H, cfg::B), 256, AT_SMEM_BYTES>>>();

    // 3) Output projection
    gemm_cp<cfg::C, 1><<<dim3(cfg::C / 128, cfg::M / 128), 256,
                         GS_SMEM_BYTES>>>(bproj, out, nullptr, nullptr, nullptr);
}